// round 1
// baseline (speedup 1.0000x reference)
#include <cuda_runtime.h>
#include <math.h>

// ---------------- problem dims (compile-time) ----------------
#define Ldim  2048
#define Bdim  8
#define Edim  1024
#define Zdim  256
#define Mrows (Ldim*Bdim)          // 16384
#define NBASE (2*Edim+Zdim)        // 2304
#define EPSV  1e-5f
#define SCALEV 0.022097086912079608f  // 1/sqrt(2048)

// ---------------- scratch (__device__ globals; no allocs) ----------------
__device__ float g_nq  [(size_t)Mrows*Edim];    // nq, later reused as h*r
__device__ float g_base[(size_t)Mrows*NBASE];   // [q_raw | u(sig) | r(silu)]
__device__ float g_q   [(size_t)Mrows*Zdim];
__device__ float g_k   [(size_t)Mrows*Zdim];
__device__ float g_v   [(size_t)Mrows*Edim];
__device__ float g_attn[(size_t)Bdim*Ldim*Ldim];
__device__ float g_h   [(size_t)Mrows*Edim];

// ---------------- helpers ----------------
__device__ __forceinline__ float sigmoidf_(float x){ return 1.f/(1.f+expf(-x)); }
__device__ __forceinline__ float siluf_(float x){ return x/(1.f+expf(-x)); }

__device__ __forceinline__ float blockReduceSum(float v) {
    __shared__ float sh[8];
    __shared__ float res;
    int lane = threadIdx.x & 31, wid = threadIdx.x >> 5;
    #pragma unroll
    for (int o = 16; o; o >>= 1) v += __shfl_xor_sync(0xffffffffu, v, o);
    if (lane == 0) sh[wid] = v;
    __syncthreads();
    if (wid == 0) {
        float t = (lane < 8) ? sh[lane] : 0.f;
        #pragma unroll
        for (int o = 4; o; o >>= 1) t += __shfl_xor_sync(0xffffffffu, t, o);
        if (lane == 0) res = t;
    }
    __syncthreads();
    return res;
}

// ---------------- layernorm over E per row ----------------
__global__ void ln_kernel(const float* __restrict__ x, const float* __restrict__ w,
                          const float* __restrict__ bvec, float* __restrict__ y)
{
    const size_t row = blockIdx.x;
    float4 xv = ((const float4*)(x + row*Edim))[threadIdx.x];
    float mu = blockReduceSum(xv.x+xv.y+xv.z+xv.w) * (1.f/Edim);
    float dx = xv.x-mu, dy = xv.y-mu, dz = xv.z-mu, dw = xv.w-mu;
    float var = blockReduceSum(dx*dx+dy*dy+dz*dz+dw*dw) * (1.f/Edim);
    float rstd = rsqrtf(var + EPSV);
    float4 wv = ((const float4*)w)[threadIdx.x];
    float4 bv = ((const float4*)bvec)[threadIdx.x];
    float4 o;
    o.x = dx*rstd*wv.x + bv.x;
    o.y = dy*rstd*wv.y + bv.y;
    o.z = dz*rstd*wv.z + bv.z;
    o.w = dw*rstd*wv.w + bv.w;
    ((float4*)(y + row*Edim))[threadIdx.x] = o;
}

// ---------------- l2norm over Z + affine (gamma+1, beta) ----------------
__global__ void l2norm_kernel(const float* __restrict__ in, int ldin,
                              float* __restrict__ out,
                              const float* __restrict__ gamma, const float* __restrict__ beta)
{
    const size_t row = blockIdx.x;
    const int z = threadIdx.x;
    float x = in[row*(size_t)ldin + z];
    float ss = blockReduceSum(x*x);
    float d = fmaxf(sqrtf(ss), EPSV);
    out[row*Zdim + z] = (x/d) * (gamma[z] + 1.f) + beta[z];
}

// ---------------- generic NT GEMM: Y = X[M,K] @ W[N,K]^T + bias, fused epilogues ----------------
#define BM 64
#define BN 64
#define BKx 16

enum { EPI_BASE=0, EPI_RAW=1, EPI_SILU=2, EPI_OUT=3 };

template<int EPI>
__global__ void gemm_nt_kernel(const float* __restrict__ X, const float* __restrict__ W,
                               const float* __restrict__ bias, float* __restrict__ Y,
                               int Kdim, int ldY,
                               const float* __restrict__ query, const float* __restrict__ ubase)
{
    __shared__ __align__(16) float Xs[BKx][BM+4];
    __shared__ __align__(16) float Ws[BKx][BN+4];
    const int tid  = threadIdx.x;
    const int row0 = blockIdx.y * BM;
    const int col0 = blockIdx.x * BN;
    const int lm = tid >> 2;
    const int lk = (tid & 3) << 2;
    const int tm = (tid >> 4) << 2;
    const int tn = (tid & 15) << 2;
    float acc[4][4] = {};
    const float* xp = X + (size_t)(row0+lm)*Kdim + lk;
    const float* wp = W + (size_t)(col0+lm)*Kdim + lk;
    for (int k0 = 0; k0 < Kdim; k0 += BKx) {
        float4 xv = *(const float4*)(xp + k0);
        float4 wv = *(const float4*)(wp + k0);
        Xs[lk+0][lm]=xv.x; Xs[lk+1][lm]=xv.y; Xs[lk+2][lm]=xv.z; Xs[lk+3][lm]=xv.w;
        Ws[lk+0][lm]=wv.x; Ws[lk+1][lm]=wv.y; Ws[lk+2][lm]=wv.z; Ws[lk+3][lm]=wv.w;
        __syncthreads();
        #pragma unroll
        for (int kk = 0; kk < BKx; kk++) {
            float4 a = *(const float4*)&Xs[kk][tm];
            float4 b = *(const float4*)&Ws[kk][tn];
            float av[4] = {a.x,a.y,a.z,a.w};
            float bv[4] = {b.x,b.y,b.z,b.w};
            #pragma unroll
            for (int i = 0; i < 4; i++)
                #pragma unroll
                for (int j = 0; j < 4; j++)
                    acc[i][j] += av[i]*bv[j];
        }
        __syncthreads();
    }
    #pragma unroll
    for (int i = 0; i < 4; i++) {
        const int r = row0 + tm + i;
        #pragma unroll
        for (int j = 0; j < 4; j++) {
            const int c = col0 + tn + j;
            float v = acc[i][j] + bias[c];
            if (EPI == EPI_BASE) {
                if (c >= Zdim) v = (c < Zdim+Edim) ? sigmoidf_(v) : siluf_(v);
            } else if (EPI == EPI_SILU) {
                v = siluf_(v);
            } else if (EPI == EPI_OUT) {
                float u  = ubase[(size_t)r*NBASE + Zdim + c];
                float qv = query[(size_t)r*Edim + c];
                v = qv + u*(v - qv);
            }
            Y[(size_t)r*ldY + c] = v;
        }
    }
}

// ---------------- attention scores: attn[b,s,c] = relu(q.k*scale + relbias)^2 ----------------
__global__ void attn_score_kernel(const float* __restrict__ Q, const float* __restrict__ Kt,
                                  const float* __restrict__ relpos, float* __restrict__ attn)
{
    __shared__ __align__(16) float Qs[BKx][BM+4];
    __shared__ __align__(16) float Ks[BKx][BN+4];
    const int b  = blockIdx.z;
    const int s0 = blockIdx.y * BM;
    const int c0 = blockIdx.x * BN;
    const int tid = threadIdx.x;
    const int lm = tid >> 2, lk = (tid & 3) << 2;
    const int tm = (tid >> 4) << 2, tn = (tid & 15) << 2;
    float acc[4][4] = {};
    const float* qp = Q  + ((size_t)(s0+lm)*Bdim + b)*Zdim + lk;
    const float* kp = Kt + ((size_t)(c0+lm)*Bdim + b)*Zdim + lk;
    for (int k0 = 0; k0 < Zdim; k0 += BKx) {
        float4 qv = *(const float4*)(qp + k0);
        float4 kv = *(const float4*)(kp + k0);
        Qs[lk+0][lm]=qv.x; Qs[lk+1][lm]=qv.y; Qs[lk+2][lm]=qv.z; Qs[lk+3][lm]=qv.w;
        Ks[lk+0][lm]=kv.x; Ks[lk+1][lm]=kv.y; Ks[lk+2][lm]=kv.z; Ks[lk+3][lm]=kv.w;
        __syncthreads();
        #pragma unroll
        for (int kk = 0; kk < BKx; kk++) {
            float4 a = *(const float4*)&Qs[kk][tm];
            float4 bb = *(const float4*)&Ks[kk][tn];
            float av[4] = {a.x,a.y,a.z,a.w};
            float bv[4] = {bb.x,bb.y,bb.z,bb.w};
            #pragma unroll
            for (int i = 0; i < 4; i++)
                #pragma unroll
                for (int j = 0; j < 4; j++)
                    acc[i][j] += av[i]*bv[j];
        }
        __syncthreads();
    }
    #pragma unroll
    for (int i = 0; i < 4; i++) {
        const int s = s0 + tm + i;
        #pragma unroll
        for (int j = 0; j < 4; j++) {
            const int c = c0 + tn + j;
            float v = acc[i][j]*SCALEV + relpos[2047 + c - s];
            v = fmaxf(v, 0.f);
            attn[((size_t)b*Ldim + s)*Ldim + c] = v*v;
        }
    }
}

// ---------------- h = attn @ v (NN, per batch, strided V rows) ----------------
__global__ void attn_v_kernel(const float* __restrict__ attn, const float* __restrict__ V,
                              float* __restrict__ H)
{
    __shared__ __align__(16) float As[BM][BKx];
    __shared__ __align__(16) float Vs[BKx][BN];
    const int b  = blockIdx.z;
    const int s0 = blockIdx.y * BM;
    const int e0 = blockIdx.x * BN;
    const int tid = threadIdx.x;
    const int lm = tid >> 2, lk = (tid & 3) << 2;   // A loader
    const int vk = tid >> 4, vn = (tid & 15) << 2;  // V loader
    const int tm = (tid >> 4) << 2, tn = (tid & 15) << 2;
    float acc[4][4] = {};
    const float* ap = attn + ((size_t)b*Ldim + s0 + lm)*Ldim + lk;
    for (int k0 = 0; k0 < Ldim; k0 += BKx) {
        *(float4*)&As[lm][lk] = *(const float4*)(ap + k0);
        *(float4*)&Vs[vk][vn] = *(const float4*)(V + ((size_t)(k0+vk)*Bdim + b)*Edim + e0 + vn);
        __syncthreads();
        #pragma unroll
        for (int kk = 0; kk < BKx; kk++) {
            float4 bb = *(const float4*)&Vs[kk][tn];
            float bv[4] = {bb.x,bb.y,bb.z,bb.w};
            float av[4] = {As[tm+0][kk], As[tm+1][kk], As[tm+2][kk], As[tm+3][kk]};
            #pragma unroll
            for (int i = 0; i < 4; i++)
                #pragma unroll
                for (int j = 0; j < 4; j++)
                    acc[i][j] += av[i]*bv[j];
        }
        __syncthreads();
    }
    #pragma unroll
    for (int i = 0; i < 4; i++) {
        float* op = H + ((size_t)(s0+tm+i)*Bdim + b)*Edim + e0 + tn;
        *(float4*)op = make_float4(acc[i][0], acc[i][1], acc[i][2], acc[i][3]);
    }
}

// ---------------- elementwise h*r (r = silu'd cols [Z+E, 2E+Z) of base) ----------------
__global__ void hr_kernel(const float* __restrict__ h, const float* __restrict__ base,
                          float* __restrict__ hr)
{
    size_t idx = (size_t)blockIdx.x*blockDim.x + threadIdx.x;  // over Mrows*E/4
    size_t m  = idx / (Edim/4);
    size_t e4 = idx % (Edim/4);
    float4 hv = ((const float4*)h)[idx];
    float4 rv = *(const float4*)(base + m*NBASE + Zdim + Edim + e4*4);
    ((float4*)hr)[idx] = make_float4(hv.x*rv.x, hv.y*rv.y, hv.z*rv.z, hv.w*rv.w);
}

// ---------------- launch ----------------
extern "C" void kernel_launch(void* const* d_in, const int* /*in_sizes*/, int /*n_in*/,
                              void* d_out, int /*out_size*/)
{
    const float* query  = (const float*)d_in[0];
    const float* key_in = (const float*)d_in[1];
    const float* value  = (const float*)d_in[2];
    const float* ln_w   = (const float*)d_in[3];
    const float* ln_b   = (const float*)d_in[4];
    const float* Wv     = (const float*)d_in[5];
    const float* bv     = (const float*)d_in[6];
    const float* Wk     = (const float*)d_in[7];
    const float* bk     = (const float*)d_in[8];
    const float* Wqru   = (const float*)d_in[9];
    const float* bqru   = (const float*)d_in[10];
    const float* Wh     = (const float*)d_in[11];
    const float* bh     = (const float*)d_in[12];
    const float* gamma  = (const float*)d_in[13];
    const float* beta   = (const float*)d_in[14];
    const float* relpos = (const float*)d_in[15];
    float* out = (float*)d_out;

    float *nq, *base, *q, *k, *v, *attn, *h;
    cudaGetSymbolAddress((void**)&nq,   g_nq);
    cudaGetSymbolAddress((void**)&base, g_base);
    cudaGetSymbolAddress((void**)&q,    g_q);
    cudaGetSymbolAddress((void**)&k,    g_k);
    cudaGetSymbolAddress((void**)&v,    g_v);
    cudaGetSymbolAddress((void**)&attn, g_attn);
    cudaGetSymbolAddress((void**)&h,    g_h);

    // 1. nq = layernorm(query)
    ln_kernel<<<Mrows, 256>>>(query, ln_w, ln_b, nq);
    // 2. base = nq @ Wqru^T + bqru  (q raw | u sigmoid | r silu fused)
    gemm_nt_kernel<EPI_BASE><<<dim3(NBASE/BN, Mrows/BM), 256>>>(nq, Wqru, bqru, base, Edim, NBASE, nullptr, nullptr);
    // 3. k = key_in @ Wk^T + bk (raw)
    gemm_nt_kernel<EPI_RAW><<<dim3(Zdim/BN, Mrows/BM), 256>>>(key_in, Wk, bk, k, Edim, Zdim, nullptr, nullptr);
    // 4. v = silu(value @ Wv^T + bv)
    gemm_nt_kernel<EPI_SILU><<<dim3(Edim/BN, Mrows/BM), 256>>>(value, Wv, bv, v, Edim, Edim, nullptr, nullptr);
    // 5. q = l2norm(base[:, :Z]) * (gamma0+1) + beta0
    l2norm_kernel<<<Mrows, 256>>>(base, NBASE, q, gamma, beta);
    // 6. k = l2norm(k) * (gamma1+1) + beta1   (in place)
    l2norm_kernel<<<Mrows, 256>>>(k, Zdim, k, gamma + Zdim, beta + Zdim);
    // 7. attn = relu(q.k*scale + relbias)^2
    attn_score_kernel<<<dim3(Ldim/BN, Ldim/BM, Bdim), 256>>>(q, k, relpos, attn);
    // 8. h = attn @ v
    attn_v_kernel<<<dim3(Edim/BN, Ldim/BM, Bdim), 256>>>(attn, v, h);
    // 9. hr = h * r  (into nq scratch)
    hr_kernel<<<(Mrows*(Edim/4))/256, 256>>>(h, base, nq);
    // 10. out = query + u * ((hr @ Wh^T + bh) - query)
    gemm_nt_kernel<EPI_OUT><<<dim3(Edim/BN, Mrows/BM), 256>>>(nq, Wh, bh, out, Edim, Edim, query, base);
}

// round 2
// speedup vs baseline: 2.3991x; 2.3991x over previous
#include <cuda_runtime.h>
#include <math.h>
#include <stdint.h>

// ---------------- problem dims (compile-time) ----------------
#define Ldim  2048
#define Bdim  8
#define Edim  1024
#define Zdim  256
#define Mrows (Ldim*Bdim)          // 16384
#define NBASE (2*Edim+Zdim)        // 2304
#define EPSV  1e-5f
#define SCALEV 0.022097086912079608f  // 1/sqrt(2048)

// ---------------- scratch (__device__ globals; no allocs) ----------------
__device__ __align__(16) float g_nq  [(size_t)Mrows*Edim];
__device__ __align__(16) float g_base[(size_t)Mrows*NBASE];   // [q_raw | u(sig) | r(silu)]
__device__ __align__(16) float g_q   [(size_t)Mrows*Zdim];
__device__ __align__(16) float g_k   [(size_t)Mrows*Zdim];
__device__ __align__(16) float g_v   [(size_t)Mrows*Edim];
__device__ __align__(16) float g_attn[(size_t)Bdim*Ldim*Ldim];
__device__ __align__(16) float g_h   [(size_t)Mrows*Edim];

// ---------------- helpers ----------------
__device__ __forceinline__ float sigmoidf_(float x){ return 1.f/(1.f+expf(-x)); }
__device__ __forceinline__ float siluf_(float x){ return x/(1.f+expf(-x)); }

__device__ __forceinline__ float to_tf32(float x){
    float r; asm("cvt.rna.tf32.f32 %0, %1;" : "=f"(r) : "f"(x)); return r;
}
__device__ __forceinline__ uint32_t fu(float x){ return __float_as_uint(x); }

__device__ __forceinline__ void mma_tf32(float* d, const uint32_t* a, const uint32_t* b){
    asm volatile(
        "mma.sync.aligned.m16n8k8.row.col.f32.tf32.tf32.f32 "
        "{%0,%1,%2,%3}, {%4,%5,%6,%7}, {%8,%9}, {%0,%1,%2,%3};\n"
        : "+f"(d[0]), "+f"(d[1]), "+f"(d[2]), "+f"(d[3])
        : "r"(a[0]), "r"(a[1]), "r"(a[2]), "r"(a[3]), "r"(b[0]), "r"(b[1]));
}

__device__ __forceinline__ float blockReduceSum(float v) {
    __shared__ float sh[8];
    __shared__ float res;
    int lane = threadIdx.x & 31, wid = threadIdx.x >> 5;
    #pragma unroll
    for (int o = 16; o; o >>= 1) v += __shfl_xor_sync(0xffffffffu, v, o);
    if (lane == 0) sh[wid] = v;
    __syncthreads();
    if (wid == 0) {
        float t = (lane < 8) ? sh[lane] : 0.f;
        #pragma unroll
        for (int o = 4; o; o >>= 1) t += __shfl_xor_sync(0xffffffffu, t, o);
        if (lane == 0) res = t;
    }
    __syncthreads();
    return res;
}

// ---------------- layernorm over E per row ----------------
__global__ void ln_kernel(const float* __restrict__ x, const float* __restrict__ w,
                          const float* __restrict__ bvec, float* __restrict__ y)
{
    const size_t row = blockIdx.x;
    float4 xv = ((const float4*)(x + row*Edim))[threadIdx.x];
    float mu = blockReduceSum(xv.x+xv.y+xv.z+xv.w) * (1.f/Edim);
    float dx = xv.x-mu, dy = xv.y-mu, dz = xv.z-mu, dw = xv.w-mu;
    float var = blockReduceSum(dx*dx+dy*dy+dz*dz+dw*dw) * (1.f/Edim);
    float rstd = rsqrtf(var + EPSV);
    float4 wv = ((const float4*)w)[threadIdx.x];
    float4 bv = ((const float4*)bvec)[threadIdx.x];
    float4 o;
    o.x = dx*rstd*wv.x + bv.x;
    o.y = dy*rstd*wv.y + bv.y;
    o.z = dz*rstd*wv.z + bv.z;
    o.w = dw*rstd*wv.w + bv.w;
    ((float4*)(y + row*Edim))[threadIdx.x] = o;
}

// ---------------- l2norm over Z + affine (gamma+1, beta) ----------------
__global__ void l2norm_kernel(const float* __restrict__ in, int ldin,
                              float* __restrict__ out,
                              const float* __restrict__ gamma, const float* __restrict__ beta)
{
    const size_t row = blockIdx.x;
    const int z = threadIdx.x;
    float x = in[row*(size_t)ldin + z];
    float ss = blockReduceSum(x*x);
    float d = fmaxf(sqrtf(ss), EPSV);
    out[row*Zdim + z] = (x/d) * (gamma[z] + 1.f) + beta[z];
}

// =====================================================================
// tf32 tensor-core GEMM: Y[M,N] = A[M,K] @ B + epilogue
//   BT=true : B is W[N,K] row-major (NT gemm)
//   BT=false: B is [K,N]-indexed with row stride sB (NN gemm)
// CTA tile 128x64x16, 8 warps (4m x 2n), warp tile 32x32, mma m16n8k8.
// =====================================================================
#define BM 128
#define BN 64
#define BK 16

enum { EPI_BASE=0, EPI_RAW=1, EPI_SILU=2, EPI_OUT=3, EPI_SCORE=4, EPI_AV=5 };

template<int EPI, bool BT>
__global__ void __launch_bounds__(256)
mma_gemm(const float* __restrict__ A, size_t sAm, size_t batchA,
         const float* __restrict__ Bp, size_t sB, size_t batchB,
         const float* __restrict__ bias,
         float* __restrict__ Y, size_t sYm, size_t batchY,
         int Kdim,
         const float* __restrict__ e0, size_t e0s, size_t batchE0,
         const float* __restrict__ e1,
         const float* __restrict__ relpos)
{
    __shared__ __align__(16) float As[BM][BK+4];   // stride 20: conflict-free frag reads
    __shared__ __align__(16) float Bs[BK][BN+8];   // stride 72: conflict-free frag reads

    const int tid  = threadIdx.x;
    const int warp = tid >> 5, lane = tid & 31;
    const int g  = lane >> 2, tg = lane & 3;
    const int wm = warp >> 1, wn = warp & 1;
    const int row0 = blockIdx.y * BM;
    const int col0 = blockIdx.x * BN;
    const int bz   = blockIdx.z;

    A  += (size_t)bz * batchA;
    Bp += (size_t)bz * batchB;
    Y  += (size_t)bz * batchY;
    const float* e0b = e0 ? e0 + (size_t)bz * batchE0 : e0;

    float acc[2][4][4];
    #pragma unroll
    for (int i=0;i<2;i++)
        #pragma unroll
        for (int j=0;j<4;j++)
            #pragma unroll
            for (int t=0;t<4;t++) acc[i][j][t]=0.f;

    const int am = tid >> 2, ak = (tid & 3) << 2;   // A loader (also BT B loader)
    const int nk = tid >> 4, nn = (tid & 15) << 2;  // NN B loader

    for (int k0 = 0; k0 < Kdim; k0 += BK) {
        // ---- load A tile (128x16), convert to tf32 ----
        #pragma unroll
        for (int l = 0; l < 2; l++) {
            int m = am + l*64;
            const float4 v = *(const float4*)(A + (size_t)(row0+m)*sAm + k0 + ak);
            float4 t; t.x=to_tf32(v.x); t.y=to_tf32(v.y); t.z=to_tf32(v.z); t.w=to_tf32(v.w);
            *(float4*)&As[m][ak] = t;
        }
        // ---- load B tile (16x64) ----
        if (BT) {
            const float4 v = *(const float4*)(Bp + (size_t)(col0+am)*sB + k0 + ak);
            Bs[ak+0][am] = to_tf32(v.x);
            Bs[ak+1][am] = to_tf32(v.y);
            Bs[ak+2][am] = to_tf32(v.z);
            Bs[ak+3][am] = to_tf32(v.w);
        } else {
            const float4 v = *(const float4*)(Bp + (size_t)(k0+nk)*sB + col0 + nn);
            float4 t; t.x=to_tf32(v.x); t.y=to_tf32(v.y); t.z=to_tf32(v.z); t.w=to_tf32(v.w);
            *(float4*)&Bs[nk][nn] = t;
        }
        __syncthreads();

        // ---- compute: 2 k-steps of k8 ----
        #pragma unroll
        for (int ks = 0; ks < 2; ks++) {
            const int kk = ks*8;
            uint32_t a[2][4], b[4][2];
            #pragma unroll
            for (int i = 0; i < 2; i++) {
                int r = wm*32 + i*16 + g;
                a[i][0] = fu(As[r  ][kk+tg  ]);
                a[i][1] = fu(As[r+8][kk+tg  ]);
                a[i][2] = fu(As[r  ][kk+tg+4]);
                a[i][3] = fu(As[r+8][kk+tg+4]);
            }
            #pragma unroll
            for (int j = 0; j < 4; j++) {
                int c = wn*32 + j*8 + g;
                b[j][0] = fu(Bs[kk+tg  ][c]);
                b[j][1] = fu(Bs[kk+tg+4][c]);
            }
            #pragma unroll
            for (int i = 0; i < 2; i++)
                #pragma unroll
                for (int j = 0; j < 4; j++)
                    mma_tf32(acc[i][j], a[i], b[j]);
        }
        __syncthreads();
    }

    // ---- epilogue ----
    #pragma unroll
    for (int i = 0; i < 2; i++) {
        #pragma unroll
        for (int j = 0; j < 4; j++) {
            const int rr = row0 + wm*32 + i*16 + g;
            const int cc = col0 + wn*32 + j*8 + tg*2;
            #pragma unroll
            for (int h = 0; h < 2; h++) {        // h=0: rows rr ; h=1: rows rr+8
                const int r = rr + h*8;
                float v0 = acc[i][j][h*2+0];
                float v1 = acc[i][j][h*2+1];
                if (EPI == EPI_BASE) {
                    v0 += bias[cc];   v1 += bias[cc+1];
                    if (cc   >= Zdim) v0 = (cc   < Zdim+Edim) ? sigmoidf_(v0) : siluf_(v0);
                    if (cc+1 >= Zdim) v1 = (cc+1 < Zdim+Edim) ? sigmoidf_(v1) : siluf_(v1);
                } else if (EPI == EPI_RAW) {
                    v0 += bias[cc];   v1 += bias[cc+1];
                } else if (EPI == EPI_SILU) {
                    v0 = siluf_(v0 + bias[cc]); v1 = siluf_(v1 + bias[cc+1]);
                } else if (EPI == EPI_OUT) {
                    v0 += bias[cc];   v1 += bias[cc+1];
                    float u0 = e0b[(size_t)r*NBASE + Zdim + cc];
                    float u1 = e0b[(size_t)r*NBASE + Zdim + cc+1];
                    float q0 = e1[(size_t)r*Edim + cc];
                    float q1 = e1[(size_t)r*Edim + cc+1];
                    v0 = q0 + u0*(v0 - q0);
                    v1 = q1 + u1*(v1 - q1);
                } else if (EPI == EPI_SCORE) {
                    v0 = fmaxf(v0*SCALEV + relpos[2047 + cc   - r], 0.f); v0 *= v0;
                    v1 = fmaxf(v1*SCALEV + relpos[2047 + cc+1 - r], 0.f); v1 *= v1;
                } else if (EPI == EPI_AV) {
                    v0 *= e0b[(size_t)r*e0s + cc];
                    v1 *= e0b[(size_t)r*e0s + cc+1];
                }
                *(float2*)(Y + (size_t)r*sYm + cc) = make_float2(v0, v1);
            }
        }
    }
}

// ---------------- launch ----------------
extern "C" void kernel_launch(void* const* d_in, const int* /*in_sizes*/, int /*n_in*/,
                              void* d_out, int /*out_size*/)
{
    const float* query  = (const float*)d_in[0];
    const float* key_in = (const float*)d_in[1];
    const float* value  = (const float*)d_in[2];
    const float* ln_w   = (const float*)d_in[3];
    const float* ln_b   = (const float*)d_in[4];
    const float* Wv     = (const float*)d_in[5];
    const float* bv     = (const float*)d_in[6];
    const float* Wk     = (const float*)d_in[7];
    const float* bk     = (const float*)d_in[8];
    const float* Wqru   = (const float*)d_in[9];
    const float* bqru   = (const float*)d_in[10];
    const float* Wh     = (const float*)d_in[11];
    const float* bh     = (const float*)d_in[12];
    const float* gamma  = (const float*)d_in[13];
    const float* beta   = (const float*)d_in[14];
    const float* relpos = (const float*)d_in[15];
    float* out = (float*)d_out;

    float *nq, *base, *q, *k, *v, *attn, *h;
    cudaGetSymbolAddress((void**)&nq,   g_nq);
    cudaGetSymbolAddress((void**)&base, g_base);
    cudaGetSymbolAddress((void**)&q,    g_q);
    cudaGetSymbolAddress((void**)&k,    g_k);
    cudaGetSymbolAddress((void**)&v,    g_v);
    cudaGetSymbolAddress((void**)&attn, g_attn);
    cudaGetSymbolAddress((void**)&h,    g_h);

    // 1. nq = layernorm(query)
    ln_kernel<<<Mrows, 256>>>(query, ln_w, ln_b, nq);

    // 2. base = nq @ Wqru^T + bqru  (raw q | sigmoid u | silu r fused)
    mma_gemm<EPI_BASE,true><<<dim3(NBASE/BN, Mrows/BM, 1), 256>>>(
        nq, Edim, 0, Wqru, Edim, 0, bqru, base, NBASE, 0, Edim,
        nullptr, 0, 0, nullptr, nullptr);

    // 3. k = key_in @ Wk^T + bk (raw)
    mma_gemm<EPI_RAW,true><<<dim3(Zdim/BN, Mrows/BM, 1), 256>>>(
        key_in, Edim, 0, Wk, Edim, 0, bk, k, Zdim, 0, Edim,
        nullptr, 0, 0, nullptr, nullptr);

    // 4. v = silu(value @ Wv^T + bv)
    mma_gemm<EPI_SILU,true><<<dim3(Edim/BN, Mrows/BM, 1), 256>>>(
        value, Edim, 0, Wv, Edim, 0, bv, v, Edim, 0, Edim,
        nullptr, 0, 0, nullptr, nullptr);

    // 5. q = l2norm(base[:, :Z]) * (gamma0+1) + beta0
    l2norm_kernel<<<Mrows, 256>>>(base, NBASE, q, gamma, beta);
    // 6. k = l2norm(k) * (gamma1+1) + beta1   (in place)
    l2norm_kernel<<<Mrows, 256>>>(k, Zdim, k, gamma + Zdim, beta + Zdim);

    // 7. attn[b,s,c] = relu(q.k*scale + relbias)^2   (batched NT)
    mma_gemm<EPI_SCORE,true><<<dim3(Ldim/BN, Ldim/BM, Bdim), 256>>>(
        q, (size_t)Bdim*Zdim, Zdim,
        k, (size_t)Bdim*Zdim, Zdim,
        nullptr, attn, Ldim, (size_t)Ldim*Ldim, Zdim,
        nullptr, 0, 0, nullptr, relpos);

    // 8. h = (attn @ v) * r    (batched NN, r fused from base)
    mma_gemm<EPI_AV,false><<<dim3(Edim/BN, Ldim/BM, Bdim), 256>>>(
        attn, Ldim, (size_t)Ldim*Ldim,
        v, (size_t)Bdim*Edim, Edim,
        nullptr, h, (size_t)Bdim*Edim, Edim, Ldim,
        base + Zdim + Edim, (size_t)Bdim*NBASE, NBASE, nullptr, nullptr);

    // 9. out = query + u * ((h.r @ Wh^T + bh) - query)
    mma_gemm<EPI_OUT,true><<<dim3(Edim/BN, Mrows/BM, 1), 256>>>(
        h, Edim, 0, Wh, Edim, 0, bh, out, Edim, 0, Edim,
        base, 0, 0, query, nullptr);
}

// round 4
// speedup vs baseline: 3.9758x; 1.6572x over previous
#include <cuda_runtime.h>
#include <math.h>
#include <stdint.h>

// ---------------- problem dims ----------------
#define Ldim  2048
#define Bdim  8
#define Edim  1024
#define Zdim  256
#define Mrows (Ldim*Bdim)          // 16384
#define NBASE (2*Edim+Zdim)        // 2304
#define EPSV  1e-5f
#define SCALEV 0.022097086912079608f  // 1/sqrt(2048)

// ---------------- scratch ----------------
__device__ __align__(16) float g_nq  [(size_t)Mrows*Edim];
__device__ __align__(16) float g_base[(size_t)Mrows*NBASE];   // [q_raw | u(sig) | r(silu)]
__device__ __align__(16) float g_q   [(size_t)Mrows*Zdim];
__device__ __align__(16) float g_k   [(size_t)Mrows*Zdim];
__device__ __align__(16) float g_v   [(size_t)Mrows*Edim];
__device__ __align__(16) float g_vt  [(size_t)Bdim*Edim*Ldim];  // v^T per batch: [b][e][c]
__device__ __align__(16) float g_attn[(size_t)Bdim*Ldim*Ldim];
__device__ __align__(16) float g_h   [(size_t)Mrows*Edim];

// ---------------- helpers ----------------
__device__ __forceinline__ float sigmoidf_(float x){ return 1.f/(1.f+expf(-x)); }
__device__ __forceinline__ float siluf_(float x){ return x/(1.f+expf(-x)); }
__device__ __forceinline__ uint32_t fu(float x){ return __float_as_uint(x); }

__device__ __forceinline__ uint32_t smem_u32(const void* p){
    uint32_t a;
    asm("{ .reg .u64 t; cvta.to.shared.u64 t, %1; cvt.u32.u64 %0, t; }" : "=r"(a) : "l"(p));
    return a;
}
__device__ __forceinline__ void cp16(uint32_t dst, const void* src){
    asm volatile("cp.async.cg.shared.global [%0], [%1], 16;" :: "r"(dst), "l"(src));
}
#define CP_COMMIT() asm volatile("cp.async.commit_group;" ::: "memory")
#define CP_WAIT1()  asm volatile("cp.async.wait_group 1;" ::: "memory")

__device__ __forceinline__ void mma_tf32(float* d, const uint32_t* a, const uint32_t* b){
    asm volatile(
        "mma.sync.aligned.m16n8k8.row.col.f32.tf32.tf32.f32 "
        "{%0,%1,%2,%3}, {%4,%5,%6,%7}, {%8,%9}, {%0,%1,%2,%3};\n"
        : "+f"(d[0]), "+f"(d[1]), "+f"(d[2]), "+f"(d[3])
        : "r"(a[0]), "r"(a[1]), "r"(a[2]), "r"(a[3]), "r"(b[0]), "r"(b[1]));
}

__device__ __forceinline__ float blockReduceSum(float v) {
    __shared__ float sh[8];
    __shared__ float res;
    int lane = threadIdx.x & 31, wid = threadIdx.x >> 5;
    #pragma unroll
    for (int o = 16; o; o >>= 1) v += __shfl_xor_sync(0xffffffffu, v, o);
    if (lane == 0) sh[wid] = v;
    __syncthreads();
    if (wid == 0) {
        float t = (lane < 8) ? sh[lane] : 0.f;
        #pragma unroll
        for (int o = 4; o; o >>= 1) t += __shfl_xor_sync(0xffffffffu, t, o);
        if (lane == 0) res = t;
    }
    __syncthreads();
    return res;
}

// ---------------- layernorm / l2norm / transpose ----------------
__global__ void ln_kernel(const float* __restrict__ x, const float* __restrict__ w,
                          const float* __restrict__ bvec, float* __restrict__ y)
{
    const size_t row = blockIdx.x;
    float4 xv = ((const float4*)(x + row*Edim))[threadIdx.x];
    float mu = blockReduceSum(xv.x+xv.y+xv.z+xv.w) * (1.f/Edim);
    float dx = xv.x-mu, dy = xv.y-mu, dz = xv.z-mu, dw = xv.w-mu;
    float var = blockReduceSum(dx*dx+dy*dy+dz*dz+dw*dw) * (1.f/Edim);
    float rstd = rsqrtf(var + EPSV);
    float4 wv = ((const float4*)w)[threadIdx.x];
    float4 bv = ((const float4*)bvec)[threadIdx.x];
    float4 o;
    o.x = dx*rstd*wv.x + bv.x;
    o.y = dy*rstd*wv.y + bv.y;
    o.z = dz*rstd*wv.z + bv.z;
    o.w = dw*rstd*wv.w + bv.w;
    ((float4*)(y + row*Edim))[threadIdx.x] = o;
}

__global__ void l2norm_kernel(const float* __restrict__ in, int ldin,
                              float* __restrict__ out,
                              const float* __restrict__ gamma, const float* __restrict__ beta)
{
    const size_t row = blockIdx.x;
    const int z = threadIdx.x;
    float x = in[row*(size_t)ldin + z];
    float ss = blockReduceSum(x*x);
    float d = fmaxf(sqrtf(ss), EPSV);
    out[row*Zdim + z] = (x/d) * (gamma[z] + 1.f) + beta[z];
}

// vt[b][e][c] = v[(c*B+b)*E + e]
__global__ void transpose_v(const float* __restrict__ v, float* __restrict__ vt)
{
    __shared__ float t[32][33];
    const int b  = blockIdx.z;
    const int c0 = blockIdx.x*32, e0 = blockIdx.y*32;
    const int x = threadIdx.x, y = threadIdx.y;
    #pragma unroll
    for (int i = 0; i < 32; i += 8)
        t[y+i][x] = v[(size_t)(c0+y+i)*Bdim*Edim + (size_t)b*Edim + e0 + x];
    __syncthreads();
    #pragma unroll
    for (int i = 0; i < 32; i += 8)
        vt[((size_t)b*Edim + e0+y+i)*Ldim + c0 + x] = t[x][y+i];
}

// =====================================================================
// tf32 HMMA GEMM (NT): Y[M,N] = A[M,K] @ B[N,K]^T + epilogue
// CTA 128x128x32, 4 warps (2x2), warp tile 64x64 (4x8 m16n8k8 tiles).
// cp.async.cg double-buffered pipeline; fp32->tf32 by HW truncation.
// =====================================================================
#define BM 128
#define BN 128
#define BK 32
#define PAD 36                       // floats per smem row (bank-spread, 16B-aligned)
#define TBYTES (128*PAD*4)           // one operand tile: 18432 B
#define BUFBYTES (2*TBYTES)          // A+B per stage: 36864 B
#define SMEM_BYTES (2*BUFBYTES)      // 73728 B

enum { EPI_BASE=0, EPI_RAW=1, EPI_SILU=2, EPI_OUT=3, EPI_SCORE=4, EPI_AV=5 };

template<int EPI>
__global__ void __launch_bounds__(128)
tc_gemm(const float* __restrict__ A, size_t sAm, size_t batchA,
        const float* __restrict__ Bp, size_t sB, size_t batchB,
        const float* __restrict__ bias,
        float* __restrict__ Y, size_t sYm, size_t batchY,
        int Kdim,
        const float* __restrict__ e0, size_t e0s, size_t batchE0,
        const float* __restrict__ e1,
        const float* __restrict__ relpos)
{
    extern __shared__ __align__(16) float smem[];
    const uint32_t smem_b = smem_u32(smem);
    const int tid  = threadIdx.x;
    const int warp = tid >> 5, lane = tid & 31;
    const int g = lane >> 2, tg = lane & 3;
    const int wm = warp >> 1, wn = warp & 1;
    const int row0 = blockIdx.y * BM;
    const int col0 = blockIdx.x * BN;
    const int bz   = blockIdx.z;

    A  += (size_t)bz * batchA;
    Bp += (size_t)bz * batchB;
    Y  += (size_t)bz * batchY;
    const float* e0b = e0 ? e0 + (size_t)bz * batchE0 : e0;

    float acc[4][8][4];
    #pragma unroll
    for (int i=0;i<4;i++)
        #pragma unroll
        for (int j=0;j<8;j++)
            #pragma unroll
            for (int t=0;t<4;t++) acc[i][j][t]=0.f;

    const int lr  = tid >> 3;            // loader row 0..15 step per i
    const int lc4 = (tid & 7) << 2;      // loader col (floats)

    const float* Ag = A  + (size_t)row0*sAm;
    const float* Bg = Bp + (size_t)col0*sB;

    // issue loads for K-tile kt into stage s
    auto load_tile = [&](int kt, int s){
        const uint32_t ab = smem_b + s*BUFBYTES;
        const uint32_t bb = ab + TBYTES;
        const float* Agk = Ag + (size_t)kt*BK;
        const float* Bgk = Bg + (size_t)kt*BK;
        #pragma unroll
        for (int i = 0; i < 8; i++) {
            int r = lr + i*16;
            cp16(ab + (uint32_t)(r*PAD + lc4)*4, Agk + (size_t)r*sAm + lc4);
            cp16(bb + (uint32_t)(r*PAD + lc4)*4, Bgk + (size_t)r*sB  + lc4);
        }
    };

    const int KT = Kdim / BK;
    load_tile(0, 0);
    CP_COMMIT();

    for (int kt = 0; kt < KT; kt++) {
        if (kt + 1 < KT) load_tile(kt+1, (kt+1)&1);
        CP_COMMIT();
        CP_WAIT1();
        __syncthreads();

        const float* Asb = smem + (kt&1)*(BUFBYTES/4);
        const float* Bsb = Asb + (TBYTES/4);
        #pragma unroll
        for (int ks = 0; ks < 4; ks++) {
            const int kk = ks*8;
            uint32_t a[4][4], b[8][2];
            #pragma unroll
            for (int i = 0; i < 4; i++) {
                const int r = wm*64 + i*16 + g;
                a[i][0] = fu(Asb[(size_t)r*PAD     + kk+tg  ]);
                a[i][1] = fu(Asb[(size_t)(r+8)*PAD + kk+tg  ]);
                a[i][2] = fu(Asb[(size_t)r*PAD     + kk+tg+4]);
                a[i][3] = fu(Asb[(size_t)(r+8)*PAD + kk+tg+4]);
            }
            #pragma unroll
            for (int j = 0; j < 8; j++) {
                const int c = wn*64 + j*8 + g;
                b[j][0] = fu(Bsb[(size_t)c*PAD + kk+tg  ]);
                b[j][1] = fu(Bsb[(size_t)c*PAD + kk+tg+4]);
            }
            #pragma unroll
            for (int i = 0; i < 4; i++)
                #pragma unroll
                for (int j = 0; j < 8; j++)
                    mma_tf32(acc[i][j], a[i], b[j]);
        }
        __syncthreads();
    }

    // ---- epilogue ----
    #pragma unroll
    for (int i = 0; i < 4; i++) {
        #pragma unroll
        for (int j = 0; j < 8; j++) {
            const int rr = row0 + wm*64 + i*16 + g;
            const int cc = col0 + wn*64 + j*8 + tg*2;
            #pragma unroll
            for (int h = 0; h < 2; h++) {
                const int r = rr + h*8;
                float v0 = acc[i][j][h*2+0];
                float v1 = acc[i][j][h*2+1];
                if (EPI == EPI_BASE) {
                    v0 += bias[cc];   v1 += bias[cc+1];
                    if (cc   >= Zdim) v0 = (cc   < Zdim+Edim) ? sigmoidf_(v0) : siluf_(v0);
                    if (cc+1 >= Zdim) v1 = (cc+1 < Zdim+Edim) ? sigmoidf_(v1) : siluf_(v1);
                } else if (EPI == EPI_RAW) {
                    v0 += bias[cc];   v1 += bias[cc+1];
                } else if (EPI == EPI_SILU) {
                    v0 = siluf_(v0 + bias[cc]); v1 = siluf_(v1 + bias[cc+1]);
                } else if (EPI == EPI_OUT) {
                    v0 += bias[cc];   v1 += bias[cc+1];
                    float u0 = e0b[(size_t)r*NBASE + Zdim + cc];
                    float u1 = e0b[(size_t)r*NBASE + Zdim + cc+1];
                    float q0 = e1[(size_t)r*Edim + cc];
                    float q1 = e1[(size_t)r*Edim + cc+1];
                    v0 = q0 + u0*(v0 - q0);
                    v1 = q1 + u1*(v1 - q1);
                } else if (EPI == EPI_SCORE) {
                    v0 = fmaxf(v0*SCALEV + relpos[2047 + cc   - r], 0.f); v0 *= v0;
                    v1 = fmaxf(v1*SCALEV + relpos[2047 + cc+1 - r], 0.f); v1 *= v1;
                } else if (EPI == EPI_AV) {
                    v0 *= e0b[(size_t)r*e0s + cc];
                    v1 *= e0b[(size_t)r*e0s + cc+1];
                }
                *(float2*)(Y + (size_t)r*sYm + cc) = make_float2(v0, v1);
            }
        }
    }
}

// ---------------- launch ----------------
extern "C" void kernel_launch(void* const* d_in, const int* /*in_sizes*/, int /*n_in*/,
                              void* d_out, int /*out_size*/)
{
    const float* query  = (const float*)d_in[0];
    const float* key_in = (const float*)d_in[1];
    const float* value  = (const float*)d_in[2];
    const float* ln_w   = (const float*)d_in[3];
    const float* ln_b   = (const float*)d_in[4];
    const float* Wv     = (const float*)d_in[5];
    const float* bv     = (const float*)d_in[6];
    const float* Wk     = (const float*)d_in[7];
    const float* bk     = (const float*)d_in[8];
    const float* Wqru   = (const float*)d_in[9];
    const float* bqru   = (const float*)d_in[10];
    const float* Wh     = (const float*)d_in[11];
    const float* bh     = (const float*)d_in[12];
    const float* gamma  = (const float*)d_in[13];
    const float* beta   = (const float*)d_in[14];
    const float* relpos = (const float*)d_in[15];
    float* out = (float*)d_out;

    float *nq, *base, *q, *k, *v, *vt, *attn, *h;
    cudaGetSymbolAddress((void**)&nq,   g_nq);
    cudaGetSymbolAddress((void**)&base, g_base);
    cudaGetSymbolAddress((void**)&q,    g_q);
    cudaGetSymbolAddress((void**)&k,    g_k);
    cudaGetSymbolAddress((void**)&v,    g_v);
    cudaGetSymbolAddress((void**)&vt,   g_vt);
    cudaGetSymbolAddress((void**)&attn, g_attn);
    cudaGetSymbolAddress((void**)&h,    g_h);

    cudaFuncSetAttribute(tc_gemm<EPI_BASE>,  cudaFuncAttributeMaxDynamicSharedMemorySize, SMEM_BYTES);
    cudaFuncSetAttribute(tc_gemm<EPI_RAW>,   cudaFuncAttributeMaxDynamicSharedMemorySize, SMEM_BYTES);
    cudaFuncSetAttribute(tc_gemm<EPI_SILU>,  cudaFuncAttributeMaxDynamicSharedMemorySize, SMEM_BYTES);
    cudaFuncSetAttribute(tc_gemm<EPI_OUT>,   cudaFuncAttributeMaxDynamicSharedMemorySize, SMEM_BYTES);
    cudaFuncSetAttribute(tc_gemm<EPI_SCORE>, cudaFuncAttributeMaxDynamicSharedMemorySize, SMEM_BYTES);
    cudaFuncSetAttribute(tc_gemm<EPI_AV>,    cudaFuncAttributeMaxDynamicSharedMemorySize, SMEM_BYTES);

    // 1. nq = layernorm(query)
    ln_kernel<<<Mrows, 256>>>(query, ln_w, ln_b, nq);

    // 2. base = nq @ Wqru^T + bqru  (raw q | sigmoid u | silu r)
    tc_gemm<EPI_BASE><<<dim3(NBASE/BN, Mrows/BM, 1), 128, SMEM_BYTES>>>(
        nq, Edim, 0, Wqru, Edim, 0, bqru, base, NBASE, 0, Edim,
        nullptr, 0, 0, nullptr, nullptr);

    // 3. k = key_in @ Wk^T + bk
    tc_gemm<EPI_RAW><<<dim3(Zdim/BN, Mrows/BM, 1), 128, SMEM_BYTES>>>(
        key_in, Edim, 0, Wk, Edim, 0, bk, k, Zdim, 0, Edim,
        nullptr, 0, 0, nullptr, nullptr);

    // 4. v = silu(value @ Wv^T + bv)
    tc_gemm<EPI_SILU><<<dim3(Edim/BN, Mrows/BM, 1), 128, SMEM_BYTES>>>(
        value, Edim, 0, Wv, Edim, 0, bv, v, Edim, 0, Edim,
        nullptr, 0, 0, nullptr, nullptr);

    // 5/6. l2norms
    l2norm_kernel<<<Mrows, 256>>>(base, NBASE, q, gamma, beta);
    l2norm_kernel<<<Mrows, 256>>>(k, Zdim, k, gamma + Zdim, beta + Zdim);

    // 6b. vt[b][e][c] = v
    transpose_v<<<dim3(Ldim/32, Edim/32, Bdim), dim3(32,8)>>>(v, vt);

    // 7. attn[b,s,c] = relu(q.k*scale + relbias)^2
    tc_gemm<EPI_SCORE><<<dim3(Ldim/BN, Ldim/BM, Bdim), 128, SMEM_BYTES>>>(
        q, (size_t)Bdim*Zdim, Zdim,
        k, (size_t)Bdim*Zdim, Zdim,
        nullptr, attn, Ldim, (size_t)Ldim*Ldim, Zdim,
        nullptr, 0, 0, nullptr, relpos);

    // 8. h = (attn @ vt^T) * r
    tc_gemm<EPI_AV><<<dim3(Edim/BN, Ldim/BM, Bdim), 128, SMEM_BYTES>>>(
        attn, Ldim, (size_t)Ldim*Ldim,
        vt, Ldim, (size_t)Edim*Ldim,
        nullptr, h, (size_t)Bdim*Edim, Edim, Ldim,
        base + Zdim + Edim, (size_t)Bdim*NBASE, NBASE, nullptr, nullptr);

    // 9. out = query + u * ((h.r @ Wh^T + bh) - query)
    tc_gemm<EPI_OUT><<<dim3(Edim/BN, Mrows/BM, 1), 128, SMEM_BYTES>>>(
        h, Edim, 0, Wh, Edim, 0, bh, out, Edim, 0, Edim,
        base, 0, 0, query, nullptr);
}

// round 5
// speedup vs baseline: 4.2671x; 1.0733x over previous
#include <cuda_runtime.h>
#include <math.h>
#include <stdint.h>

// ---------------- problem dims ----------------
#define Ldim  2048
#define Bdim  8
#define Edim  1024
#define Zdim  256
#define Mrows (Ldim*Bdim)          // 16384
#define NBASE (2*Edim+Zdim)        // 2304
#define EPSV  1e-5f
#define SCALEV 0.022097086912079608f  // 1/sqrt(2048)

// ---------------- scratch ----------------
__device__ __align__(16) float g_nq  [(size_t)Mrows*Edim];
__device__ __align__(16) float g_base[(size_t)Mrows*NBASE];   // [q_raw | u(sig) | r(silu)]
__device__ __align__(16) float g_q   [(size_t)Mrows*Zdim];
__device__ __align__(16) float g_k   [(size_t)Mrows*Zdim];
__device__ __align__(16) float g_v   [(size_t)Mrows*Edim];
__device__ __align__(16) float g_vt  [(size_t)Bdim*Edim*Ldim];  // v^T per batch: [b][e][c]
__device__ __align__(16) float g_attn[(size_t)Bdim*Ldim*Ldim];
__device__ __align__(16) float g_h   [(size_t)Mrows*Edim];

// ---------------- helpers ----------------
__device__ __forceinline__ float sigmoidf_(float x){ return 1.f/(1.f+expf(-x)); }
__device__ __forceinline__ float siluf_(float x){ return x/(1.f+expf(-x)); }
__device__ __forceinline__ uint32_t fu(float x){ return __float_as_uint(x); }

__device__ __forceinline__ uint32_t smem_u32(const void* p){
    uint32_t a;
    asm("{ .reg .u64 t; cvta.to.shared.u64 t, %1; cvt.u32.u64 %0, t; }" : "=r"(a) : "l"(p));
    return a;
}
__device__ __forceinline__ void cp16(uint32_t dst, const void* src){
    asm volatile("cp.async.cg.shared.global [%0], [%1], 16;" :: "r"(dst), "l"(src));
}
#define CP_COMMIT() asm volatile("cp.async.commit_group;" ::: "memory")
#define CP_WAIT1()  asm volatile("cp.async.wait_group 1;" ::: "memory")

__device__ __forceinline__ void mma_tf32(float* d, const uint32_t* a, const uint32_t* b){
    asm volatile(
        "mma.sync.aligned.m16n8k8.row.col.f32.tf32.tf32.f32 "
        "{%0,%1,%2,%3}, {%4,%5,%6,%7}, {%8,%9}, {%0,%1,%2,%3};\n"
        : "+f"(d[0]), "+f"(d[1]), "+f"(d[2]), "+f"(d[3])
        : "r"(a[0]), "r"(a[1]), "r"(a[2]), "r"(a[3]), "r"(b[0]), "r"(b[1]));
}

__device__ __forceinline__ float blockReduceSum(float v) {
    __shared__ float sh[8];
    __shared__ float res;
    int lane = threadIdx.x & 31, wid = threadIdx.x >> 5;
    #pragma unroll
    for (int o = 16; o; o >>= 1) v += __shfl_xor_sync(0xffffffffu, v, o);
    if (lane == 0) sh[wid] = v;
    __syncthreads();
    if (wid == 0) {
        float t = (lane < 8) ? sh[lane] : 0.f;
        #pragma unroll
        for (int o = 4; o; o >>= 1) t += __shfl_xor_sync(0xffffffffu, t, o);
        if (lane == 0) res = t;
    }
    __syncthreads();
    return res;
}

// ---------------- layernorm / l2norm / transpose ----------------
__global__ void ln_kernel(const float* __restrict__ x, const float* __restrict__ w,
                          const float* __restrict__ bvec, float* __restrict__ y)
{
    const size_t row = blockIdx.x;
    float4 xv = ((const float4*)(x + row*Edim))[threadIdx.x];
    float mu = blockReduceSum(xv.x+xv.y+xv.z+xv.w) * (1.f/Edim);
    float dx = xv.x-mu, dy = xv.y-mu, dz = xv.z-mu, dw = xv.w-mu;
    float var = blockReduceSum(dx*dx+dy*dy+dz*dz+dw*dw) * (1.f/Edim);
    float rstd = rsqrtf(var + EPSV);
    float4 wv = ((const float4*)w)[threadIdx.x];
    float4 bv = ((const float4*)bvec)[threadIdx.x];
    float4 o;
    o.x = dx*rstd*wv.x + bv.x;
    o.y = dy*rstd*wv.y + bv.y;
    o.z = dz*rstd*wv.z + bv.z;
    o.w = dw*rstd*wv.w + bv.w;
    ((float4*)(y + row*Edim))[threadIdx.x] = o;
}

__global__ void l2norm_kernel(const float* __restrict__ in, int ldin,
                              float* __restrict__ out,
                              const float* __restrict__ gamma, const float* __restrict__ beta)
{
    const size_t row = blockIdx.x;
    const int z = threadIdx.x;
    float x = in[row*(size_t)ldin + z];
    float ss = blockReduceSum(x*x);
    float d = fmaxf(sqrtf(ss), EPSV);
    out[row*Zdim + z] = (x/d) * (gamma[z] + 1.f) + beta[z];
}

// vt[b][e][c] = v[(c*B+b)*E + e]
__global__ void transpose_v(const float* __restrict__ v, float* __restrict__ vt)
{
    __shared__ float t[32][33];
    const int b  = blockIdx.z;
    const int c0 = blockIdx.x*32, e0 = blockIdx.y*32;
    const int x = threadIdx.x, y = threadIdx.y;
    #pragma unroll
    for (int i = 0; i < 32; i += 8)
        t[y+i][x] = v[(size_t)(c0+y+i)*Bdim*Edim + (size_t)b*Edim + e0 + x];
    __syncthreads();
    #pragma unroll
    for (int i = 0; i < 32; i += 8)
        vt[((size_t)b*Edim + e0+y+i)*Ldim + c0 + x] = t[x][y+i];
}

// =====================================================================
// tf32 HMMA GEMM (NT): Y[M,N] = A[M,K] @ B[N,K]^T + epilogue
// CTA 128x128x32, 8 warps (4m x 2n), warp tile 32x64 (2x8 m16n8k8).
// 3-stage cp.async pipeline, one __syncthreads per K-tile.
// =====================================================================
#define BM 128
#define BN 128
#define BK 32
#define NSTAGE 3
#define PAD 36                       // floats per smem row (conflict-free, 16B-aligned)
#define TBYTES (128*PAD*4)           // one operand tile: 18432 B
#define BUFBYTES (2*TBYTES)          // A+B per stage: 36864 B
#define SMEM_BYTES (NSTAGE*BUFBYTES) // 110592 B

enum { EPI_BASE=0, EPI_RAW=1, EPI_SILU=2, EPI_OUT=3, EPI_SCORE=4, EPI_AV=5 };

template<int EPI>
__global__ void __launch_bounds__(256, 2)
tc_gemm(const float* __restrict__ A, size_t sAm, size_t batchA,
        const float* __restrict__ Bp, size_t sB, size_t batchB,
        const float* __restrict__ bias,
        float* __restrict__ Y, size_t sYm, size_t batchY,
        int Kdim,
        const float* __restrict__ e0, size_t e0s, size_t batchE0,
        const float* __restrict__ e1,
        const float* __restrict__ relpos)
{
    extern __shared__ __align__(16) float smem[];
    const uint32_t smem_b = smem_u32(smem);
    const int tid  = threadIdx.x;
    const int warp = tid >> 5, lane = tid & 31;
    const int g = lane >> 2, tg = lane & 3;
    const int wm = warp >> 1, wn = warp & 1;     // 4 x 2 warps
    const int row0 = blockIdx.y * BM;
    const int col0 = blockIdx.x * BN;
    const int bz   = blockIdx.z;

    A  += (size_t)bz * batchA;
    Bp += (size_t)bz * batchB;
    Y  += (size_t)bz * batchY;
    const float* e0b = e0 ? e0 + (size_t)bz * batchE0 : e0;

    float acc[2][8][4];
    #pragma unroll
    for (int i=0;i<2;i++)
        #pragma unroll
        for (int j=0;j<8;j++)
            #pragma unroll
            for (int t=0;t<4;t++) acc[i][j][t]=0.f;

    const int lr  = tid >> 3;            // loader row 0..31
    const int lc4 = (tid & 7) << 2;      // loader col (floats)

    const float* Ag = A  + (size_t)row0*sAm;
    const float* Bg = Bp + (size_t)col0*sB;

    auto load_tile = [&](int kt, int s){
        const uint32_t ab = smem_b + s*BUFBYTES;
        const uint32_t bb = ab + TBYTES;
        const float* Agk = Ag + (size_t)kt*BK;
        const float* Bgk = Bg + (size_t)kt*BK;
        #pragma unroll
        for (int i = 0; i < 4; i++) {
            int r = lr + i*32;
            cp16(ab + (uint32_t)(r*PAD + lc4)*4, Agk + (size_t)r*sAm + lc4);
            cp16(bb + (uint32_t)(r*PAD + lc4)*4, Bgk + (size_t)r*sB  + lc4);
        }
    };

    const int KT = Kdim / BK;
    load_tile(0, 0); CP_COMMIT();
    if (KT > 1) { load_tile(1, 1); } CP_COMMIT();

    for (int kt = 0; kt < KT; kt++) {
        CP_WAIT1();            // stage kt resident
        __syncthreads();       // visibility + reuse protection for stage (kt+2)%3

        const float* Asb = smem + (kt % NSTAGE)*(BUFBYTES/4);
        const float* Bsb = Asb + (TBYTES/4);
        #pragma unroll
        for (int ks = 0; ks < 4; ks++) {
            const int kk = ks*8;
            uint32_t a[2][4], b[8][2];
            #pragma unroll
            for (int i = 0; i < 2; i++) {
                const int r = wm*32 + i*16 + g;
                a[i][0] = fu(Asb[(size_t)r*PAD     + kk+tg  ]);
                a[i][1] = fu(Asb[(size_t)(r+8)*PAD + kk+tg  ]);
                a[i][2] = fu(Asb[(size_t)r*PAD     + kk+tg+4]);
                a[i][3] = fu(Asb[(size_t)(r+8)*PAD + kk+tg+4]);
            }
            #pragma unroll
            for (int j = 0; j < 8; j++) {
                const int c = wn*64 + j*8 + g;
                b[j][0] = fu(Bsb[(size_t)c*PAD + kk+tg  ]);
                b[j][1] = fu(Bsb[(size_t)c*PAD + kk+tg+4]);
            }
            #pragma unroll
            for (int i = 0; i < 2; i++)
                #pragma unroll
                for (int j = 0; j < 8; j++)
                    mma_tf32(acc[i][j], a[i], b[j]);
        }

        if (kt + 2 < KT) load_tile(kt+2, (kt+2) % NSTAGE);
        CP_COMMIT();
    }

    // ---- epilogue ----
    #pragma unroll
    for (int i = 0; i < 2; i++) {
        #pragma unroll
        for (int j = 0; j < 8; j++) {
            const int rr = row0 + wm*32 + i*16 + g;
            const int cc = col0 + wn*64 + j*8 + tg*2;
            #pragma unroll
            for (int h = 0; h < 2; h++) {
                const int r = rr + h*8;
                float v0 = acc[i][j][h*2+0];
                float v1 = acc[i][j][h*2+1];
                if (EPI == EPI_BASE) {
                    v0 += bias[cc];   v1 += bias[cc+1];
                    if (cc   >= Zdim) v0 = (cc   < Zdim+Edim) ? sigmoidf_(v0) : siluf_(v0);
                    if (cc+1 >= Zdim) v1 = (cc+1 < Zdim+Edim) ? sigmoidf_(v1) : siluf_(v1);
                } else if (EPI == EPI_RAW) {
                    v0 += bias[cc];   v1 += bias[cc+1];
                } else if (EPI == EPI_SILU) {
                    v0 = siluf_(v0 + bias[cc]); v1 = siluf_(v1 + bias[cc+1]);
                } else if (EPI == EPI_OUT) {
                    v0 += bias[cc];   v1 += bias[cc+1];
                    float u0 = e0b[(size_t)r*NBASE + Zdim + cc];
                    float u1 = e0b[(size_t)r*NBASE + Zdim + cc+1];
                    float q0 = e1[(size_t)r*Edim + cc];
                    float q1 = e1[(size_t)r*Edim + cc+1];
                    v0 = q0 + u0*(v0 - q0);
                    v1 = q1 + u1*(v1 - q1);
                } else if (EPI == EPI_SCORE) {
                    v0 = fmaxf(v0*SCALEV + relpos[2047 + cc   - r], 0.f); v0 *= v0;
                    v1 = fmaxf(v1*SCALEV + relpos[2047 + cc+1 - r], 0.f); v1 *= v1;
                } else if (EPI == EPI_AV) {
                    v0 *= e0b[(size_t)r*e0s + cc];
                    v1 *= e0b[(size_t)r*e0s + cc+1];
                }
                *(float2*)(Y + (size_t)r*sYm + cc) = make_float2(v0, v1);
            }
        }
    }
}

// ---------------- launch ----------------
extern "C" void kernel_launch(void* const* d_in, const int* /*in_sizes*/, int /*n_in*/,
                              void* d_out, int /*out_size*/)
{
    const float* query  = (const float*)d_in[0];
    const float* key_in = (const float*)d_in[1];
    const float* value  = (const float*)d_in[2];
    const float* ln_w   = (const float*)d_in[3];
    const float* ln_b   = (const float*)d_in[4];
    const float* Wv     = (const float*)d_in[5];
    const float* bv     = (const float*)d_in[6];
    const float* Wk     = (const float*)d_in[7];
    const float* bk     = (const float*)d_in[8];
    const float* Wqru   = (const float*)d_in[9];
    const float* bqru   = (const float*)d_in[10];
    const float* Wh     = (const float*)d_in[11];
    const float* bh     = (const float*)d_in[12];
    const float* gamma  = (const float*)d_in[13];
    const float* beta   = (const float*)d_in[14];
    const float* relpos = (const float*)d_in[15];
    float* out = (float*)d_out;

    float *nq, *base, *q, *k, *v, *vt, *attn, *h;
    cudaGetSymbolAddress((void**)&nq,   g_nq);
    cudaGetSymbolAddress((void**)&base, g_base);
    cudaGetSymbolAddress((void**)&q,    g_q);
    cudaGetSymbolAddress((void**)&k,    g_k);
    cudaGetSymbolAddress((void**)&v,    g_v);
    cudaGetSymbolAddress((void**)&vt,   g_vt);
    cudaGetSymbolAddress((void**)&attn, g_attn);
    cudaGetSymbolAddress((void**)&h,    g_h);

    cudaFuncSetAttribute(tc_gemm<EPI_BASE>,  cudaFuncAttributeMaxDynamicSharedMemorySize, SMEM_BYTES);
    cudaFuncSetAttribute(tc_gemm<EPI_RAW>,   cudaFuncAttributeMaxDynamicSharedMemorySize, SMEM_BYTES);
    cudaFuncSetAttribute(tc_gemm<EPI_SILU>,  cudaFuncAttributeMaxDynamicSharedMemorySize, SMEM_BYTES);
    cudaFuncSetAttribute(tc_gemm<EPI_OUT>,   cudaFuncAttributeMaxDynamicSharedMemorySize, SMEM_BYTES);
    cudaFuncSetAttribute(tc_gemm<EPI_SCORE>, cudaFuncAttributeMaxDynamicSharedMemorySize, SMEM_BYTES);
    cudaFuncSetAttribute(tc_gemm<EPI_AV>,    cudaFuncAttributeMaxDynamicSharedMemorySize, SMEM_BYTES);

    // 1. nq = layernorm(query)
    ln_kernel<<<Mrows, 256>>>(query, ln_w, ln_b, nq);

    // 2. base = nq @ Wqru^T + bqru  (raw q | sigmoid u | silu r)
    tc_gemm<EPI_BASE><<<dim3(NBASE/BN, Mrows/BM, 1), 256, SMEM_BYTES>>>(
        nq, Edim, 0, Wqru, Edim, 0, bqru, base, NBASE, 0, Edim,
        nullptr, 0, 0, nullptr, nullptr);

    // 3. k = key_in @ Wk^T + bk
    tc_gemm<EPI_RAW><<<dim3(Zdim/BN, Mrows/BM, 1), 256, SMEM_BYTES>>>(
        key_in, Edim, 0, Wk, Edim, 0, bk, k, Zdim, 0, Edim,
        nullptr, 0, 0, nullptr, nullptr);

    // 4. v = silu(value @ Wv^T + bv)
    tc_gemm<EPI_SILU><<<dim3(Edim/BN, Mrows/BM, 1), 256, SMEM_BYTES>>>(
        value, Edim, 0, Wv, Edim, 0, bv, v, Edim, 0, Edim,
        nullptr, 0, 0, nullptr, nullptr);

    // 5/6. l2norms
    l2norm_kernel<<<Mrows, 256>>>(base, NBASE, q, gamma, beta);
    l2norm_kernel<<<Mrows, 256>>>(k, Zdim, k, gamma + Zdim, beta + Zdim);

    // 6b. vt[b][e][c] = v
    transpose_v<<<dim3(Ldim/32, Edim/32, Bdim), dim3(32,8)>>>(v, vt);

    // 7. attn[b,s,c] = relu(q.k*scale + relbias)^2
    tc_gemm<EPI_SCORE><<<dim3(Ldim/BN, Ldim/BM, Bdim), 256, SMEM_BYTES>>>(
        q, (size_t)Bdim*Zdim, Zdim,
        k, (size_t)Bdim*Zdim, Zdim,
        nullptr, attn, Ldim, (size_t)Ldim*Ldim, Zdim,
        nullptr, 0, 0, nullptr, relpos);

    // 8. h = (attn @ vt^T) * r
    tc_gemm<EPI_AV><<<dim3(Edim/BN, Ldim/BM, Bdim), 256, SMEM_BYTES>>>(
        attn, Ldim, (size_t)Ldim*Ldim,
        vt, Ldim, (size_t)Edim*Ldim,
        nullptr, h, (size_t)Bdim*Edim, Edim, Ldim,
        base + Zdim + Edim, (size_t)Bdim*NBASE, NBASE, nullptr, nullptr);

    // 9. out = query + u * ((h.r @ Wh^T + bh) - query)
    tc_gemm<EPI_OUT><<<dim3(Edim/BN, Mrows/BM, 1), 256, SMEM_BYTES>>>(
        h, Edim, 0, Wh, Edim, 0, bh, out, Edim, 0, Edim,
        base, 0, 0, query, nullptr);
}

// round 6
// speedup vs baseline: 4.5459x; 1.0653x over previous
#include <cuda_runtime.h>
#include <math.h>
#include <stdint.h>

// ---------------- problem dims ----------------
#define Ldim  2048
#define Bdim  8
#define Edim  1024
#define Zdim  256
#define Mrows (Ldim*Bdim)          // 16384
#define NBASE (2*Edim+Zdim)        // 2304
#define EPSV  1e-5f
#define SCALEV 0.022097086912079608f  // 1/sqrt(2048)

// ---------------- scratch ----------------
__device__ __align__(16) float g_nq  [(size_t)Mrows*Edim];
__device__ __align__(16) float g_base[(size_t)Mrows*NBASE];   // [q_raw | u(sig) | r(silu)]
__device__ __align__(16) float g_q   [(size_t)Mrows*Zdim];
__device__ __align__(16) float g_k   [(size_t)Mrows*Zdim];
__device__ __align__(16) float g_v   [(size_t)Mrows*Edim];
__device__ __align__(16) float g_vt  [(size_t)Bdim*Edim*Ldim];  // v^T per batch: [b][e][c]
__device__ __align__(16) float g_attn[(size_t)Bdim*Ldim*Ldim];
__device__ __align__(16) float g_h   [(size_t)Mrows*Edim];

// ---------------- helpers ----------------
__device__ __forceinline__ float sigmoidf_(float x){ return 1.f/(1.f+expf(-x)); }
__device__ __forceinline__ float siluf_(float x){ return x/(1.f+expf(-x)); }

__device__ __forceinline__ uint32_t smem_u32(const void* p){
    uint32_t a;
    asm("{ .reg .u64 t; cvta.to.shared.u64 t, %1; cvt.u32.u64 %0, t; }" : "=r"(a) : "l"(p));
    return a;
}
__device__ __forceinline__ void cp16(uint32_t dst, const void* src){
    asm volatile("cp.async.cg.shared.global [%0], [%1], 16;" :: "r"(dst), "l"(src));
}
#define CP_COMMIT() asm volatile("cp.async.commit_group;" ::: "memory")
#define CP_WAIT1()  asm volatile("cp.async.wait_group 1;" ::: "memory")

#define LDSM4(r0,r1,r2,r3,addr) \
    asm volatile("ldmatrix.sync.aligned.m8n8.x4.shared.b16 {%0,%1,%2,%3}, [%4];" \
                 : "=r"(r0),"=r"(r1),"=r"(r2),"=r"(r3) : "r"(addr))

__device__ __forceinline__ void mma_tf32(float* d, const uint32_t* a, const uint32_t* b){
    asm volatile(
        "mma.sync.aligned.m16n8k8.row.col.f32.tf32.tf32.f32 "
        "{%0,%1,%2,%3}, {%4,%5,%6,%7}, {%8,%9}, {%0,%1,%2,%3};\n"
        : "+f"(d[0]), "+f"(d[1]), "+f"(d[2]), "+f"(d[3])
        : "r"(a[0]), "r"(a[1]), "r"(a[2]), "r"(a[3]), "r"(b[0]), "r"(b[1]));
}

__device__ __forceinline__ float blockReduceSum(float v) {
    __shared__ float sh[8];
    __shared__ float res;
    int lane = threadIdx.x & 31, wid = threadIdx.x >> 5;
    #pragma unroll
    for (int o = 16; o; o >>= 1) v += __shfl_xor_sync(0xffffffffu, v, o);
    if (lane == 0) sh[wid] = v;
    __syncthreads();
    if (wid == 0) {
        float t = (lane < 8) ? sh[lane] : 0.f;
        #pragma unroll
        for (int o = 4; o; o >>= 1) t += __shfl_xor_sync(0xffffffffu, t, o);
        if (lane == 0) res = t;
    }
    __syncthreads();
    return res;
}

// ---------------- layernorm / l2norm / transpose ----------------
__global__ void ln_kernel(const float* __restrict__ x, const float* __restrict__ w,
                          const float* __restrict__ bvec, float* __restrict__ y)
{
    const size_t row = blockIdx.x;
    float4 xv = ((const float4*)(x + row*Edim))[threadIdx.x];
    float mu = blockReduceSum(xv.x+xv.y+xv.z+xv.w) * (1.f/Edim);
    float dx = xv.x-mu, dy = xv.y-mu, dz = xv.z-mu, dw = xv.w-mu;
    float var = blockReduceSum(dx*dx+dy*dy+dz*dz+dw*dw) * (1.f/Edim);
    float rstd = rsqrtf(var + EPSV);
    float4 wv = ((const float4*)w)[threadIdx.x];
    float4 bv = ((const float4*)bvec)[threadIdx.x];
    float4 o;
    o.x = dx*rstd*wv.x + bv.x;
    o.y = dy*rstd*wv.y + bv.y;
    o.z = dz*rstd*wv.z + bv.z;
    o.w = dw*rstd*wv.w + bv.w;
    ((float4*)(y + row*Edim))[threadIdx.x] = o;
}

__global__ void l2norm_kernel(const float* __restrict__ in, int ldin,
                              float* __restrict__ out,
                              const float* __restrict__ gamma, const float* __restrict__ beta)
{
    const size_t row = blockIdx.x;
    const int z = threadIdx.x;
    float x = in[row*(size_t)ldin + z];
    float ss = blockReduceSum(x*x);
    float d = fmaxf(sqrtf(ss), EPSV);
    out[row*Zdim + z] = (x/d) * (gamma[z] + 1.f) + beta[z];
}

// vt[b][e][c] = v[(c*B+b)*E + e]
__global__ void transpose_v(const float* __restrict__ v, float* __restrict__ vt)
{
    __shared__ float t[32][33];
    const int b  = blockIdx.z;
    const int c0 = blockIdx.x*32, e0 = blockIdx.y*32;
    const int x = threadIdx.x, y = threadIdx.y;
    #pragma unroll
    for (int i = 0; i < 32; i += 8)
        t[y+i][x] = v[(size_t)(c0+y+i)*Bdim*Edim + (size_t)b*Edim + e0 + x];
    __syncthreads();
    #pragma unroll
    for (int i = 0; i < 32; i += 8)
        vt[((size_t)b*Edim + e0+y+i)*Ldim + c0 + x] = t[x][y+i];
}

// =====================================================================
// tf32 HMMA GEMM (NT): Y[M,N] = A[M,K] @ B[N,K]^T + epilogue
// CTA 128x128x32, 8 warps (4m x 2n), warp tile 32x64 (2x8 m16n8k8).
// 3-stage cp.async pipeline; ldmatrix.x4 fragment feeding.
// =====================================================================
#define BM 128
#define BN 128
#define BK 32
#define NSTAGE 3
#define PAD 36                       // floats per smem row (conflict-free, 16B-aligned)
#define TBYTES (128*PAD*4)           // one operand tile: 18432 B
#define BUFBYTES (2*TBYTES)          // A+B per stage: 36864 B
#define SMEM_BYTES (NSTAGE*BUFBYTES) // 110592 B

enum { EPI_BASE=0, EPI_RAW=1, EPI_SILU=2, EPI_OUT=3, EPI_SCORE=4, EPI_AV=5 };

template<int EPI>
__global__ void __launch_bounds__(256, 2)
tc_gemm(const float* __restrict__ A, size_t sAm, size_t batchA,
        const float* __restrict__ Bp, size_t sB, size_t batchB,
        const float* __restrict__ bias,
        float* __restrict__ Y, size_t sYm, size_t batchY,
        int Kdim,
        const float* __restrict__ e0, size_t e0s, size_t batchE0,
        const float* __restrict__ e1,
        const float* __restrict__ relpos)
{
    extern __shared__ __align__(16) float smem[];
    const uint32_t smem_b = smem_u32(smem);
    const int tid  = threadIdx.x;
    const int warp = tid >> 5, lane = tid & 31;
    const int g = lane >> 2, tg = lane & 3;
    const int wm = warp >> 1, wn = warp & 1;     // 4 x 2 warps
    const int row0 = blockIdx.y * BM;
    const int col0 = blockIdx.x * BN;
    const int bz   = blockIdx.z;

    A  += (size_t)bz * batchA;
    Bp += (size_t)bz * batchB;
    Y  += (size_t)bz * batchY;
    const float* e0b = e0 ? e0 + (size_t)bz * batchE0 : e0;

    float acc[2][8][4];
    #pragma unroll
    for (int i=0;i<2;i++)
        #pragma unroll
        for (int j=0;j<8;j++)
            #pragma unroll
            for (int t=0;t<4;t++) acc[i][j][t]=0.f;

    // ---- ldmatrix lane addresses (stage 0; add stage/ks byte offsets later) ----
    // A frag a[i][0..3]: matrices (rows base..+7,col kk),(rows+8,kk),(base,kk+4),(+8,kk+4)
    const int lm8 = lane & 7, lq = lane >> 3;   // lq = matrix index 0..3
    uint32_t a_addr[2], b_addr[4];
    #pragma unroll
    for (int i = 0; i < 2; i++) {
        int r = wm*32 + i*16 + (lq & 1)*8 + lm8;
        int c = (lq >> 1) * 4;
        a_addr[i] = smem_b + (uint32_t)(r*PAD + c)*4;
    }
    // B frag pair (b[2jj],b[2jj+1]): matrices (rows n0..+7,kk),(n0,kk+4),(n0+8,kk),(n0+8,kk+4)
    #pragma unroll
    for (int jj = 0; jj < 4; jj++) {
        int r = wn*64 + jj*16 + (lq >> 1)*8 + lm8;
        int c = (lq & 1) * 4;
        b_addr[jj] = smem_b + TBYTES + (uint32_t)(r*PAD + c)*4;
    }

    const int lr  = tid >> 3;            // loader row 0..31
    const int lc4 = (tid & 7) << 2;      // loader col (floats)

    const float* Ag = A  + (size_t)row0*sAm;
    const float* Bg = Bp + (size_t)col0*sB;

    auto load_tile = [&](int kt, int s){
        const uint32_t ab = smem_b + s*BUFBYTES;
        const uint32_t bb = ab + TBYTES;
        const float* Agk = Ag + (size_t)kt*BK;
        const float* Bgk = Bg + (size_t)kt*BK;
        #pragma unroll
        for (int i = 0; i < 4; i++) {
            int r = lr + i*32;
            cp16(ab + (uint32_t)(r*PAD + lc4)*4, Agk + (size_t)r*sAm + lc4);
            cp16(bb + (uint32_t)(r*PAD + lc4)*4, Bgk + (size_t)r*sB  + lc4);
        }
    };

    const int KT = Kdim / BK;
    load_tile(0, 0); CP_COMMIT();
    if (KT > 1) { load_tile(1, 1); } CP_COMMIT();

    for (int kt = 0; kt < KT; kt++) {
        CP_WAIT1();            // stage kt resident
        __syncthreads();       // visibility + reuse protection

        const uint32_t soff = (uint32_t)((kt % NSTAGE)*BUFBYTES);
        #pragma unroll
        for (int ks = 0; ks < 4; ks++) {
            const uint32_t koff = soff + ks*32;   // 8 floats per ks step
            uint32_t a[2][4], b[8][2];
            LDSM4(a[0][0], a[0][1], a[0][2], a[0][3], a_addr[0] + koff);
            LDSM4(a[1][0], a[1][1], a[1][2], a[1][3], a_addr[1] + koff);
            #pragma unroll
            for (int jj = 0; jj < 4; jj++)
                LDSM4(b[2*jj][0], b[2*jj][1], b[2*jj+1][0], b[2*jj+1][1], b_addr[jj] + koff);
            #pragma unroll
            for (int i = 0; i < 2; i++)
                #pragma unroll
                for (int j = 0; j < 8; j++)
                    mma_tf32(acc[i][j], a[i], b[j]);
        }

        if (kt + 2 < KT) load_tile(kt+2, (kt+2) % NSTAGE);
        CP_COMMIT();
    }

    // ---- epilogue ----
    #pragma unroll
    for (int i = 0; i < 2; i++) {
        #pragma unroll
        for (int j = 0; j < 8; j++) {
            const int rr = row0 + wm*32 + i*16 + g;
            const int cc = col0 + wn*64 + j*8 + tg*2;
            #pragma unroll
            for (int h = 0; h < 2; h++) {
                const int r = rr + h*8;
                float v0 = acc[i][j][h*2+0];
                float v1 = acc[i][j][h*2+1];
                if (EPI == EPI_BASE) {
                    v0 += bias[cc];   v1 += bias[cc+1];
                    if (cc   >= Zdim) v0 = (cc   < Zdim+Edim) ? sigmoidf_(v0) : siluf_(v0);
                    if (cc+1 >= Zdim) v1 = (cc+1 < Zdim+Edim) ? sigmoidf_(v1) : siluf_(v1);
                } else if (EPI == EPI_RAW) {
                    v0 += bias[cc];   v1 += bias[cc+1];
                } else if (EPI == EPI_SILU) {
                    v0 = siluf_(v0 + bias[cc]); v1 = siluf_(v1 + bias[cc+1]);
                } else if (EPI == EPI_OUT) {
                    v0 += bias[cc];   v1 += bias[cc+1];
                    float u0 = e0b[(size_t)r*NBASE + Zdim + cc];
                    float u1 = e0b[(size_t)r*NBASE + Zdim + cc+1];
                    float q0 = e1[(size_t)r*Edim + cc];
                    float q1 = e1[(size_t)r*Edim + cc+1];
                    v0 = q0 + u0*(v0 - q0);
                    v1 = q1 + u1*(v1 - q1);
                } else if (EPI == EPI_SCORE) {
                    v0 = fmaxf(v0*SCALEV + relpos[2047 + cc   - r], 0.f); v0 *= v0;
                    v1 = fmaxf(v1*SCALEV + relpos[2047 + cc+1 - r], 0.f); v1 *= v1;
                } else if (EPI == EPI_AV) {
                    v0 *= e0b[(size_t)r*e0s + cc];
                    v1 *= e0b[(size_t)r*e0s + cc+1];
                }
                *(float2*)(Y + (size_t)r*sYm + cc) = make_float2(v0, v1);
            }
        }
    }
}

// ---------------- launch ----------------
extern "C" void kernel_launch(void* const* d_in, const int* /*in_sizes*/, int /*n_in*/,
                              void* d_out, int /*out_size*/)
{
    const float* query  = (const float*)d_in[0];
    const float* key_in = (const float*)d_in[1];
    const float* value  = (const float*)d_in[2];
    const float* ln_w   = (const float*)d_in[3];
    const float* ln_b   = (const float*)d_in[4];
    const float* Wv     = (const float*)d_in[5];
    const float* bv     = (const float*)d_in[6];
    const float* Wk     = (const float*)d_in[7];
    const float* bk     = (const float*)d_in[8];
    const float* Wqru   = (const float*)d_in[9];
    const float* bqru   = (const float*)d_in[10];
    const float* Wh     = (const float*)d_in[11];
    const float* bh     = (const float*)d_in[12];
    const float* gamma  = (const float*)d_in[13];
    const float* beta   = (const float*)d_in[14];
    const float* relpos = (const float*)d_in[15];
    float* out = (float*)d_out;

    float *nq, *base, *q, *k, *v, *vt, *attn, *h;
    cudaGetSymbolAddress((void**)&nq,   g_nq);
    cudaGetSymbolAddress((void**)&base, g_base);
    cudaGetSymbolAddress((void**)&q,    g_q);
    cudaGetSymbolAddress((void**)&k,    g_k);
    cudaGetSymbolAddress((void**)&v,    g_v);
    cudaGetSymbolAddress((void**)&vt,   g_vt);
    cudaGetSymbolAddress((void**)&attn, g_attn);
    cudaGetSymbolAddress((void**)&h,    g_h);

    cudaFuncSetAttribute(tc_gemm<EPI_BASE>,  cudaFuncAttributeMaxDynamicSharedMemorySize, SMEM_BYTES);
    cudaFuncSetAttribute(tc_gemm<EPI_RAW>,   cudaFuncAttributeMaxDynamicSharedMemorySize, SMEM_BYTES);
    cudaFuncSetAttribute(tc_gemm<EPI_SILU>,  cudaFuncAttributeMaxDynamicSharedMemorySize, SMEM_BYTES);
    cudaFuncSetAttribute(tc_gemm<EPI_OUT>,   cudaFuncAttributeMaxDynamicSharedMemorySize, SMEM_BYTES);
    cudaFuncSetAttribute(tc_gemm<EPI_SCORE>, cudaFuncAttributeMaxDynamicSharedMemorySize, SMEM_BYTES);
    cudaFuncSetAttribute(tc_gemm<EPI_AV>,    cudaFuncAttributeMaxDynamicSharedMemorySize, SMEM_BYTES);

    // 1. nq = layernorm(query)
    ln_kernel<<<Mrows, 256>>>(query, ln_w, ln_b, nq);

    // 2. base = nq @ Wqru^T + bqru  (raw q | sigmoid u | silu r)
    tc_gemm<EPI_BASE><<<dim3(NBASE/BN, Mrows/BM, 1), 256, SMEM_BYTES>>>(
        nq, Edim, 0, Wqru, Edim, 0, bqru, base, NBASE, 0, Edim,
        nullptr, 0, 0, nullptr, nullptr);

    // 3. k = key_in @ Wk^T + bk
    tc_gemm<EPI_RAW><<<dim3(Zdim/BN, Mrows/BM, 1), 256, SMEM_BYTES>>>(
        key_in, Edim, 0, Wk, Edim, 0, bk, k, Zdim, 0, Edim,
        nullptr, 0, 0, nullptr, nullptr);

    // 4. v = silu(value @ Wv^T + bv)
    tc_gemm<EPI_SILU><<<dim3(Edim/BN, Mrows/BM, 1), 256, SMEM_BYTES>>>(
        value, Edim, 0, Wv, Edim, 0, bv, v, Edim, 0, Edim,
        nullptr, 0, 0, nullptr, nullptr);

    // 5/6. l2norms
    l2norm_kernel<<<Mrows, 256>>>(base, NBASE, q, gamma, beta);
    l2norm_kernel<<<Mrows, 256>>>(k, Zdim, k, gamma + Zdim, beta + Zdim);

    // 6b. vt[b][e][c] = v
    transpose_v<<<dim3(Ldim/32, Edim/32, Bdim), dim3(32,8)>>>(v, vt);

    // 7. attn[b,s,c] = relu(q.k*scale + relbias)^2
    tc_gemm<EPI_SCORE><<<dim3(Ldim/BN, Ldim/BM, Bdim), 256, SMEM_BYTES>>>(
        q, (size_t)Bdim*Zdim, Zdim,
        k, (size_t)Bdim*Zdim, Zdim,
        nullptr, attn, Ldim, (size_t)Ldim*Ldim, Zdim,
        nullptr, 0, 0, nullptr, relpos);

    // 8. h = (attn @ vt^T) * r
    tc_gemm<EPI_AV><<<dim3(Edim/BN, Ldim/BM, Bdim), 256, SMEM_BYTES>>>(
        attn, Ldim, (size_t)Ldim*Ldim,
        vt, Ldim, (size_t)Edim*Ldim,
        nullptr, h, (size_t)Bdim*Edim, Edim, Ldim,
        base + Zdim + Edim, (size_t)Bdim*NBASE, NBASE, nullptr, nullptr);

    // 9. out = query + u * ((h.r @ Wh^T + bh) - query)
    tc_gemm<EPI_OUT><<<dim3(Edim/BN, Mrows/BM, 1), 256, SMEM_BYTES>>>(
        h, Edim, 0, Wh, Edim, 0, bh, out, Edim, 0, Edim,
        base, 0, 0, query, nullptr);
}

// round 7
// speedup vs baseline: 6.0262x; 1.3256x over previous
#include <cuda_runtime.h>
#include <cuda_bf16.h>
#include <math.h>
#include <stdint.h>

// ---------------- problem dims ----------------
#define Ldim  2048
#define Bdim  8
#define Edim  1024
#define Zdim  256
#define Mrows (Ldim*Bdim)          // 16384
#define NBASE (2*Edim+Zdim)        // 2304
#define EPSV  1e-5f
#define SCALEV 0.022097086912079608f  // 1/sqrt(2048)

typedef __nv_bfloat16 bf16;
typedef __nv_bfloat162 bf162;

// ---------------- scratch ----------------
__device__ __align__(16) float g_nq   [(size_t)Mrows*Edim];
__device__ __align__(16) float g_base [(size_t)Mrows*NBASE];    // [q_raw | u(sig) | r(silu)]
__device__ __align__(16) float g_kf   [(size_t)Mrows*Zdim];     // k pre-l2norm (fp32)
__device__ __align__(16) bf16  g_khin [(size_t)Mrows*Edim];     // key_in bf16
__device__ __align__(16) bf16  g_vhin [(size_t)Mrows*Edim];     // value bf16
__device__ __align__(16) bf16  g_wkh  [(size_t)Zdim*Edim];
__device__ __align__(16) bf16  g_wvh  [(size_t)Edim*Edim];
__device__ __align__(16) bf16  g_whh  [(size_t)Edim*Edim];
__device__ __align__(16) bf16  g_qh   [(size_t)Mrows*Zdim];
__device__ __align__(16) bf16  g_kh   [(size_t)Mrows*Zdim];
__device__ __align__(16) bf16  g_vh   [(size_t)Mrows*Edim];
__device__ __align__(16) bf16  g_vth  [(size_t)Bdim*Edim*Ldim]; // v^T per batch [b][e][c]
__device__ __align__(16) bf16  g_attnh[(size_t)Bdim*Ldim*Ldim];
__device__ __align__(16) bf16  g_hh   [(size_t)Mrows*Edim];     // h*r bf16

// ---------------- helpers ----------------
__device__ __forceinline__ float sigmoidf_(float x){ return 1.f/(1.f+expf(-x)); }
__device__ __forceinline__ float siluf_(float x){ return x/(1.f+expf(-x)); }

__device__ __forceinline__ uint32_t smem_u32(const void* p){
    uint32_t a;
    asm("{ .reg .u64 t; cvta.to.shared.u64 t, %1; cvt.u32.u64 %0, t; }" : "=r"(a) : "l"(p));
    return a;
}
__device__ __forceinline__ void cp16(uint32_t dst, const void* src){
    asm volatile("cp.async.cg.shared.global [%0], [%1], 16;" :: "r"(dst), "l"(src));
}
#define CP_COMMIT() asm volatile("cp.async.commit_group;" ::: "memory")
#define CP_WAIT1()  asm volatile("cp.async.wait_group 1;" ::: "memory")

#define LDSM4(r0,r1,r2,r3,addr) \
    asm volatile("ldmatrix.sync.aligned.m8n8.x4.shared.b16 {%0,%1,%2,%3}, [%4];" \
                 : "=r"(r0),"=r"(r1),"=r"(r2),"=r"(r3) : "r"(addr))

__device__ __forceinline__ void mma_tf32(float* d, const uint32_t* a, const uint32_t* b){
    asm volatile(
        "mma.sync.aligned.m16n8k8.row.col.f32.tf32.tf32.f32 "
        "{%0,%1,%2,%3}, {%4,%5,%6,%7}, {%8,%9}, {%0,%1,%2,%3};\n"
        : "+f"(d[0]), "+f"(d[1]), "+f"(d[2]), "+f"(d[3])
        : "r"(a[0]), "r"(a[1]), "r"(a[2]), "r"(a[3]), "r"(b[0]), "r"(b[1]));
}
__device__ __forceinline__ void mma_bf16(float* d, const uint32_t* a, const uint32_t* b){
    asm volatile(
        "mma.sync.aligned.m16n8k16.row.col.f32.bf16.bf16.f32 "
        "{%0,%1,%2,%3}, {%4,%5,%6,%7}, {%8,%9}, {%0,%1,%2,%3};\n"
        : "+f"(d[0]), "+f"(d[1]), "+f"(d[2]), "+f"(d[3])
        : "r"(a[0]), "r"(a[1]), "r"(a[2]), "r"(a[3]), "r"(b[0]), "r"(b[1]));
}

__device__ __forceinline__ float blockReduceSum(float v) {
    __shared__ float sh[8];
    __shared__ float res;
    int lane = threadIdx.x & 31, wid = threadIdx.x >> 5;
    #pragma unroll
    for (int o = 16; o; o >>= 1) v += __shfl_xor_sync(0xffffffffu, v, o);
    if (lane == 0) sh[wid] = v;
    __syncthreads();
    if (wid == 0) {
        float t = (lane < 8) ? sh[lane] : 0.f;
        #pragma unroll
        for (int o = 4; o; o >>= 1) t += __shfl_xor_sync(0xffffffffu, t, o);
        if (lane == 0) res = t;
    }
    __syncthreads();
    return res;
}

// ---------------- elementwise kernels ----------------
__global__ void f2bf_kernel(const float* __restrict__ x, bf16* __restrict__ y)
{
    size_t i = ((size_t)blockIdx.x*blockDim.x + threadIdx.x)*4;
    float4 v = *(const float4*)(x + i);
    bf162 o0, o1;
    o0.x = __float2bfloat16(v.x); o0.y = __float2bfloat16(v.y);
    o1.x = __float2bfloat16(v.z); o1.y = __float2bfloat16(v.w);
    *(bf162*)(y + i)     = o0;
    *(bf162*)(y + i + 2) = o1;
}

__global__ void ln_kernel(const float* __restrict__ x, const float* __restrict__ w,
                          const float* __restrict__ bvec, float* __restrict__ y)
{
    const size_t row = blockIdx.x;
    float4 xv = ((const float4*)(x + row*Edim))[threadIdx.x];
    float mu = blockReduceSum(xv.x+xv.y+xv.z+xv.w) * (1.f/Edim);
    float dx = xv.x-mu, dy = xv.y-mu, dz = xv.z-mu, dw = xv.w-mu;
    float var = blockReduceSum(dx*dx+dy*dy+dz*dz+dw*dw) * (1.f/Edim);
    float rstd = rsqrtf(var + EPSV);
    float4 wv = ((const float4*)w)[threadIdx.x];
    float4 bv = ((const float4*)bvec)[threadIdx.x];
    float4 o;
    o.x = dx*rstd*wv.x + bv.x;
    o.y = dy*rstd*wv.y + bv.y;
    o.z = dz*rstd*wv.z + bv.z;
    o.w = dw*rstd*wv.w + bv.w;
    ((float4*)(y + row*Edim))[threadIdx.x] = o;
}

// l2norm + affine, bf16 output
__global__ void l2norm_kernel(const float* __restrict__ in, int ldin,
                              bf16* __restrict__ out,
                              const float* __restrict__ gamma, const float* __restrict__ beta)
{
    const size_t row = blockIdx.x;
    const int z = threadIdx.x;
    float x = in[row*(size_t)ldin + z];
    float ss = blockReduceSum(x*x);
    float d = fmaxf(sqrtf(ss), EPSV);
    out[row*Zdim + z] = __float2bfloat16((x/d) * (gamma[z] + 1.f) + beta[z]);
}

// vt[b][e][c] = v[(c*B+b)*E + e]   (bf16)
__global__ void transpose_v(const bf16* __restrict__ v, bf16* __restrict__ vt)
{
    __shared__ bf16 t[32][33];
    const int b  = blockIdx.z;
    const int c0 = blockIdx.x*32, e0 = blockIdx.y*32;
    const int x = threadIdx.x, y = threadIdx.y;
    #pragma unroll
    for (int i = 0; i < 32; i += 8)
        t[y+i][x] = v[(size_t)(c0+y+i)*Bdim*Edim + (size_t)b*Edim + e0 + x];
    __syncthreads();
    #pragma unroll
    for (int i = 0; i < 32; i += 8)
        vt[((size_t)b*Edim + e0+y+i)*Ldim + c0 + x] = t[x][y+i];
}

enum { EPI_BASE=0, EPI_RAW=1, EPI_SILU=2, EPI_OUT=3, EPI_SCORE=4, EPI_AV=5 };

// =====================================================================
// tf32 HMMA GEMM (NT) — used only for the base projection (u precision)
// CTA 128x128x32, 8 warps, warp tile 32x64; 3-stage cp.async; ldmatrix.
// =====================================================================
#define BM 128
#define BN 128
#define BK 32
#define NSTAGE 3
#define PAD 36
#define TBYTES (128*PAD*4)
#define BUFBYTES (2*TBYTES)
#define SMEM_BYTES (NSTAGE*BUFBYTES) // 110592

template<int EPI>
__global__ void __launch_bounds__(256, 2)
tc_gemm(const float* __restrict__ A, size_t sAm,
        const float* __restrict__ Bp, size_t sB,
        const float* __restrict__ bias,
        float* __restrict__ Y, size_t sYm, int Kdim)
{
    extern __shared__ __align__(16) float smem[];
    const uint32_t smem_b = smem_u32(smem);
    const int tid  = threadIdx.x;
    const int warp = tid >> 5, lane = tid & 31;
    const int g = lane >> 2, tg = lane & 3;
    const int wm = warp >> 1, wn = warp & 1;
    const int row0 = blockIdx.y * BM;
    const int col0 = blockIdx.x * BN;

    float acc[2][8][4];
    #pragma unroll
    for (int i=0;i<2;i++)
        #pragma unroll
        for (int j=0;j<8;j++)
            #pragma unroll
            for (int t=0;t<4;t++) acc[i][j][t]=0.f;

    const int lm8 = lane & 7, lq = lane >> 3;
    uint32_t a_addr[2], b_addr[4];
    #pragma unroll
    for (int i = 0; i < 2; i++)
        a_addr[i] = smem_b + (uint32_t)((wm*32 + i*16 + (lq&1)*8 + lm8)*PAD + (lq>>1)*4)*4;
    #pragma unroll
    for (int jj = 0; jj < 4; jj++)
        b_addr[jj] = smem_b + TBYTES + (uint32_t)((wn*64 + jj*16 + (lq>>1)*8 + lm8)*PAD + (lq&1)*4)*4;

    const int lr  = tid >> 3;
    const int lc4 = (tid & 7) << 2;
    const float* Ag = A  + (size_t)row0*sAm;
    const float* Bg = Bp + (size_t)col0*sB;

    auto load_tile = [&](int kt, int s){
        const uint32_t ab = smem_b + s*BUFBYTES;
        const uint32_t bb = ab + TBYTES;
        const float* Agk = Ag + (size_t)kt*BK;
        const float* Bgk = Bp == nullptr ? nullptr : Bg + (size_t)kt*BK;
        #pragma unroll
        for (int i = 0; i < 4; i++) {
            int r = lr + i*32;
            cp16(ab + (uint32_t)(r*PAD + lc4)*4, Agk + (size_t)r*sAm + lc4);
            cp16(bb + (uint32_t)(r*PAD + lc4)*4, Bgk + (size_t)r*sB  + lc4);
        }
    };

    const int KT = Kdim / BK;
    load_tile(0, 0); CP_COMMIT();
    if (KT > 1) { load_tile(1, 1); } CP_COMMIT();

    for (int kt = 0; kt < KT; kt++) {
        CP_WAIT1();
        __syncthreads();
        const uint32_t soff = (uint32_t)((kt % NSTAGE)*BUFBYTES);
        #pragma unroll
        for (int ks = 0; ks < 4; ks++) {
            const uint32_t koff = soff + ks*32;
            uint32_t a[2][4], b[8][2];
            LDSM4(a[0][0], a[0][1], a[0][2], a[0][3], a_addr[0] + koff);
            LDSM4(a[1][0], a[1][1], a[1][2], a[1][3], a_addr[1] + koff);
            #pragma unroll
            for (int jj = 0; jj < 4; jj++)
                LDSM4(b[2*jj][0], b[2*jj][1], b[2*jj+1][0], b[2*jj+1][1], b_addr[jj] + koff);
            #pragma unroll
            for (int i = 0; i < 2; i++)
                #pragma unroll
                for (int j = 0; j < 8; j++)
                    mma_tf32(acc[i][j], a[i], b[j]);
        }
        if (kt + 2 < KT) load_tile(kt+2, (kt+2) % NSTAGE);
        CP_COMMIT();
    }

    #pragma unroll
    for (int i = 0; i < 2; i++) {
        #pragma unroll
        for (int j = 0; j < 8; j++) {
            const int rr = row0 + wm*32 + i*16 + g;
            const int cc = col0 + wn*64 + j*8 + tg*2;
            #pragma unroll
            for (int h = 0; h < 2; h++) {
                const int r = rr + h*8;
                float v0 = acc[i][j][h*2+0] + bias[cc];
                float v1 = acc[i][j][h*2+1] + bias[cc+1];
                if (EPI == EPI_BASE) {
                    if (cc   >= Zdim) v0 = (cc   < Zdim+Edim) ? sigmoidf_(v0) : siluf_(v0);
                    if (cc+1 >= Zdim) v1 = (cc+1 < Zdim+Edim) ? sigmoidf_(v1) : siluf_(v1);
                }
                *(float2*)(Y + (size_t)r*sYm + cc) = make_float2(v0, v1);
            }
        }
    }
}

// =====================================================================
// bf16 HMMA GEMM (NT): same structure, m16n8k16, BK=64 bf16.
// =====================================================================
#define HBK 64
#define HPAD 72                       // bf16 elems per row (144 B, 16B-aligned, LDSM conflict-free)
#define HTB (128*HPAD*2)              // 18432 B
#define HBUF (2*HTB)                  // 36864 B
#define HSMEM (NSTAGE*HBUF)           // 110592 B

template<int EPI, bool OUT_BF16>
__global__ void __launch_bounds__(256, 2)
hgemm(const bf16* __restrict__ A, size_t sAm, size_t batchA,
      const bf16* __restrict__ Bp, size_t sB, size_t batchB,
      const float* __restrict__ bias,
      void* __restrict__ Yv, size_t sYm, size_t batchY,
      int Kdim,
      const float* __restrict__ e0, size_t e0s, size_t batchE0,
      const float* __restrict__ e1,
      const float* __restrict__ relpos)
{
    extern __shared__ __align__(16) char hsm[];
    const uint32_t smem_b = smem_u32(hsm);
    const int tid  = threadIdx.x;
    const int warp = tid >> 5, lane = tid & 31;
    const int g = lane >> 2, tg = lane & 3;
    const int wm = warp >> 1, wn = warp & 1;
    const int row0 = blockIdx.y * BM;
    const int col0 = blockIdx.x * BN;
    const int bz   = blockIdx.z;

    A  += (size_t)bz * batchA;
    Bp += (size_t)bz * batchB;
    const float* e0b = e0 ? e0 + (size_t)bz * batchE0 : e0;

    float acc[2][8][4];
    #pragma unroll
    for (int i=0;i<2;i++)
        #pragma unroll
        for (int j=0;j<8;j++)
            #pragma unroll
            for (int t=0;t<4;t++) acc[i][j][t]=0.f;

    const int lm8 = lane & 7, lq = lane >> 3;
    uint32_t a_addr[2], b_addr[4];
    #pragma unroll
    for (int i = 0; i < 2; i++)
        a_addr[i] = smem_b + (uint32_t)((wm*32 + i*16 + (lq&1)*8 + lm8)*144 + (lq>>1)*16);
    #pragma unroll
    for (int jj = 0; jj < 4; jj++)
        b_addr[jj] = smem_b + HTB + (uint32_t)((wn*64 + jj*16 + (lq>>1)*8 + lm8)*144 + (lq&1)*16);

    const int lr  = tid >> 3;            // row 0..31
    const int lc8 = (tid & 7) << 3;      // col in bf16 elems (8 per 16B seg)
    const bf16* Ag = A  + (size_t)row0*sAm;
    const bf16* Bg = Bp + (size_t)col0*sB;

    auto load_tile = [&](int kt, int s){
        const uint32_t ab = smem_b + s*HBUF;
        const uint32_t bb = ab + HTB;
        const bf16* Agk = Ag + (size_t)kt*HBK;
        const bf16* Bgk = Bg + (size_t)kt*HBK;
        #pragma unroll
        for (int i = 0; i < 4; i++) {
            int r = lr + i*32;
            cp16(ab + (uint32_t)(r*144 + lc8*2), Agk + (size_t)r*sAm + lc8);
            cp16(bb + (uint32_t)(r*144 + lc8*2), Bgk + (size_t)r*sB  + lc8);
        }
    };

    const int KT = Kdim / HBK;
    load_tile(0, 0); CP_COMMIT();
    if (KT > 1) { load_tile(1, 1); } CP_COMMIT();

    for (int kt = 0; kt < KT; kt++) {
        CP_WAIT1();
        __syncthreads();
        const uint32_t soff = (uint32_t)((kt % NSTAGE)*HBUF);
        #pragma unroll
        for (int ks = 0; ks < 4; ks++) {
            const uint32_t koff = soff + ks*32;    // 16 bf16 per ks = 32 B
            uint32_t a[2][4], b[8][2];
            LDSM4(a[0][0], a[0][1], a[0][2], a[0][3], a_addr[0] + koff);
            LDSM4(a[1][0], a[1][1], a[1][2], a[1][3], a_addr[1] + koff);
            #pragma unroll
            for (int jj = 0; jj < 4; jj++)
                LDSM4(b[2*jj][0], b[2*jj][1], b[2*jj+1][0], b[2*jj+1][1], b_addr[jj] + koff);
            #pragma unroll
            for (int i = 0; i < 2; i++)
                #pragma unroll
                for (int j = 0; j < 8; j++)
                    mma_bf16(acc[i][j], a[i], b[j]);
        }
        if (kt + 2 < KT) load_tile(kt+2, (kt+2) % NSTAGE);
        CP_COMMIT();
    }

    // ---- epilogue ----
    #pragma unroll
    for (int i = 0; i < 2; i++) {
        #pragma unroll
        for (int j = 0; j < 8; j++) {
            const int rr = row0 + wm*32 + i*16 + g;
            const int cc = col0 + wn*64 + j*8 + tg*2;
            #pragma unroll
            for (int h = 0; h < 2; h++) {
                const int r = rr + h*8;
                float v0 = acc[i][j][h*2+0];
                float v1 = acc[i][j][h*2+1];
                if (EPI == EPI_RAW) {
                    v0 += bias[cc];   v1 += bias[cc+1];
                } else if (EPI == EPI_SILU) {
                    v0 = siluf_(v0 + bias[cc]); v1 = siluf_(v1 + bias[cc+1]);
                } else if (EPI == EPI_OUT) {
                    v0 += bias[cc];   v1 += bias[cc+1];
                    float u0 = e0b[(size_t)r*NBASE + Zdim + cc];
                    float u1 = e0b[(size_t)r*NBASE + Zdim + cc+1];
                    float q0 = e1[(size_t)r*Edim + cc];
                    float q1 = e1[(size_t)r*Edim + cc+1];
                    v0 = q0 + u0*(v0 - q0);
                    v1 = q1 + u1*(v1 - q1);
                } else if (EPI == EPI_SCORE) {
                    v0 = fmaxf(v0*SCALEV + relpos[2047 + cc   - r], 0.f); v0 *= v0;
                    v1 = fmaxf(v1*SCALEV + relpos[2047 + cc+1 - r], 0.f); v1 *= v1;
                } else if (EPI == EPI_AV) {
                    v0 *= e0b[(size_t)r*e0s + cc];
                    v1 *= e0b[(size_t)r*e0s + cc+1];
                }
                if (OUT_BF16) {
                    bf16* Y = (bf16*)Yv + (size_t)bz*batchY;
                    bf162 o; o.x = __float2bfloat16(v0); o.y = __float2bfloat16(v1);
                    *(bf162*)(Y + (size_t)r*sYm + cc) = o;
                } else {
                    float* Y = (float*)Yv + (size_t)bz*batchY;
                    *(float2*)(Y + (size_t)r*sYm + cc) = make_float2(v0, v1);
                }
            }
        }
    }
}

// ---------------- launch ----------------
extern "C" void kernel_launch(void* const* d_in, const int* /*in_sizes*/, int /*n_in*/,
                              void* d_out, int /*out_size*/)
{
    const float* query  = (const float*)d_in[0];
    const float* key_in = (const float*)d_in[1];
    const float* value  = (const float*)d_in[2];
    const float* ln_w   = (const float*)d_in[3];
    const float* ln_b   = (const float*)d_in[4];
    const float* Wv     = (const float*)d_in[5];
    const float* bv     = (const float*)d_in[6];
    const float* Wk     = (const float*)d_in[7];
    const float* bk     = (const float*)d_in[8];
    const float* Wqru   = (const float*)d_in[9];
    const float* bqru   = (const float*)d_in[10];
    const float* Wh     = (const float*)d_in[11];
    const float* bh     = (const float*)d_in[12];
    const float* gamma  = (const float*)d_in[13];
    const float* beta   = (const float*)d_in[14];
    const float* relpos = (const float*)d_in[15];
    float* out = (float*)d_out;

    float *nq, *base, *kf;
    bf16 *khin, *vhin, *wkh, *wvh, *whh, *qh, *kh, *vh, *vth, *attnh, *hh;
    cudaGetSymbolAddress((void**)&nq,    g_nq);
    cudaGetSymbolAddress((void**)&base,  g_base);
    cudaGetSymbolAddress((void**)&kf,    g_kf);
    cudaGetSymbolAddress((void**)&khin,  g_khin);
    cudaGetSymbolAddress((void**)&vhin,  g_vhin);
    cudaGetSymbolAddress((void**)&wkh,   g_wkh);
    cudaGetSymbolAddress((void**)&wvh,   g_wvh);
    cudaGetSymbolAddress((void**)&whh,   g_whh);
    cudaGetSymbolAddress((void**)&qh,    g_qh);
    cudaGetSymbolAddress((void**)&kh,    g_kh);
    cudaGetSymbolAddress((void**)&vh,    g_vh);
    cudaGetSymbolAddress((void**)&vth,   g_vth);
    cudaGetSymbolAddress((void**)&attnh, g_attnh);
    cudaGetSymbolAddress((void**)&hh,    g_hh);

    cudaFuncSetAttribute(tc_gemm<EPI_BASE>,        cudaFuncAttributeMaxDynamicSharedMemorySize, SMEM_BYTES);
    cudaFuncSetAttribute(hgemm<EPI_RAW,  false>,   cudaFuncAttributeMaxDynamicSharedMemorySize, HSMEM);
    cudaFuncSetAttribute(hgemm<EPI_SILU, true>,    cudaFuncAttributeMaxDynamicSharedMemorySize, HSMEM);
    cudaFuncSetAttribute(hgemm<EPI_SCORE,true>,    cudaFuncAttributeMaxDynamicSharedMemorySize, HSMEM);
    cudaFuncSetAttribute(hgemm<EPI_AV,   true>,    cudaFuncAttributeMaxDynamicSharedMemorySize, HSMEM);
    cudaFuncSetAttribute(hgemm<EPI_OUT,  false>,   cudaFuncAttributeMaxDynamicSharedMemorySize, HSMEM);

    // conversions to bf16
    f2bf_kernel<<<(size_t)Mrows*Edim/1024, 256>>>(key_in, khin);
    f2bf_kernel<<<(size_t)Mrows*Edim/1024, 256>>>(value,  vhin);
    f2bf_kernel<<<(size_t)Zdim*Edim/1024,  256>>>(Wk, wkh);
    f2bf_kernel<<<(size_t)Edim*Edim/1024,  256>>>(Wv, wvh);
    f2bf_kernel<<<(size_t)Edim*Edim/1024,  256>>>(Wh, whh);

    // 1. nq = layernorm(query)
    ln_kernel<<<Mrows, 256>>>(query, ln_w, ln_b, nq);

    // 2. base = nq @ Wqru^T + bqru  (tf32 — protects u precision)
    tc_gemm<EPI_BASE><<<dim3(NBASE/BN, Mrows/BM), 256, SMEM_BYTES>>>(
        nq, Edim, Wqru, Edim, bqru, base, NBASE, Edim);

    // 3. kf = key_in @ Wk^T + bk   (bf16 -> fp32 out)
    hgemm<EPI_RAW,false><<<dim3(Zdim/BN, Mrows/BM, 1), 256, HSMEM>>>(
        khin, Edim, 0, wkh, Edim, 0, bk, kf, Zdim, 0, Edim,
        nullptr, 0, 0, nullptr, nullptr);

    // 4. vh = silu(value @ Wv^T + bv)  (bf16 out)
    hgemm<EPI_SILU,true><<<dim3(Edim/BN, Mrows/BM, 1), 256, HSMEM>>>(
        vhin, Edim, 0, wvh, Edim, 0, bv, vh, Edim, 0, Edim,
        nullptr, 0, 0, nullptr, nullptr);

    // 5/6. l2norms -> bf16 q,k
    l2norm_kernel<<<Mrows, 256>>>(base, NBASE, qh, gamma, beta);
    l2norm_kernel<<<Mrows, 256>>>(kf, Zdim, kh, gamma + Zdim, beta + Zdim);

    // 6b. vth[b][e][c]
    transpose_v<<<dim3(Ldim/32, Edim/32, Bdim), dim3(32,8)>>>(vh, vth);

    // 7. attn = relu(q.k*scale + relbias)^2  (bf16)
    hgemm<EPI_SCORE,true><<<dim3(Ldim/BN, Ldim/BM, Bdim), 256, HSMEM>>>(
        qh, (size_t)Bdim*Zdim, Zdim,
        kh, (size_t)Bdim*Zdim, Zdim,
        nullptr, attnh, Ldim, (size_t)Ldim*Ldim, Zdim,
        nullptr, 0, 0, nullptr, relpos);

    // 8. hh = (attn @ vth^T) * r   (bf16 out)
    hgemm<EPI_AV,true><<<dim3(Edim/BN, Ldim/BM, Bdim), 256, HSMEM>>>(
        attnh, Ldim, (size_t)Ldim*Ldim,
        vth, Ldim, (size_t)Edim*Ldim,
        nullptr, hh, (size_t)Bdim*Edim, Edim, Ldim,
        base + Zdim + Edim, (size_t)Bdim*NBASE, NBASE, nullptr, nullptr);

    // 9. out = query + u * ((hh @ Wh^T + bh) - query)   (bf16 gemm, fp32 out)
    hgemm<EPI_OUT,false><<<dim3(Edim/BN, Mrows/BM, 1), 256, HSMEM>>>(
        hh, Edim, 0, whh, Edim, 0, bh, out, Edim, 0, Edim,
        base, 0, 0, query, nullptr);
}

// round 8
// speedup vs baseline: 6.6275x; 1.0998x over previous
#include <cuda_runtime.h>
#include <cuda_bf16.h>
#include <math.h>
#include <stdint.h>

// ---------------- problem dims ----------------
#define Ldim  2048
#define Bdim  8
#define Edim  1024
#define Zdim  256
#define Mrows (Ldim*Bdim)          // 16384
#define NBASE (2*Edim+Zdim)        // 2304
#define NQR   (Zdim+Edim)          // 1280 packed q|r cols
#define EPSV  1e-5f
#define SCALEV 0.022097086912079608f  // 1/sqrt(2048)

typedef __nv_bfloat16 bf16;
typedef __nv_bfloat162 bf162;

// ---------------- scratch ----------------
__device__ __align__(16) float g_nq   [(size_t)Mrows*Edim];
__device__ __align__(16) bf16  g_nqh  [(size_t)Mrows*Edim];
__device__ __align__(16) float g_base [(size_t)Mrows*NBASE];    // [q_raw | u(sig) | r(silu)]
__device__ __align__(16) float g_kf   [(size_t)Mrows*Zdim];     // k pre-l2norm (fp32)
__device__ __align__(16) bf16  g_khin [(size_t)Mrows*Edim];     // key_in bf16
__device__ __align__(16) bf16  g_vhin [(size_t)Mrows*Edim];     // value bf16
__device__ __align__(16) bf16  g_wkh  [(size_t)Zdim*Edim];
__device__ __align__(16) bf16  g_wvh  [(size_t)Edim*Edim];
__device__ __align__(16) bf16  g_whh  [(size_t)Edim*Edim];
__device__ __align__(16) bf16  g_wqrh [(size_t)NQR*Edim];       // packed [q rows | r rows]
__device__ __align__(16) bf16  g_qh   [(size_t)Mrows*Zdim];
__device__ __align__(16) bf16  g_kh   [(size_t)Mrows*Zdim];
__device__ __align__(16) bf16  g_vh   [(size_t)Mrows*Edim];
__device__ __align__(16) bf16  g_vth  [(size_t)Bdim*Edim*Ldim]; // v^T per batch [b][e][c]
__device__ __align__(16) bf16  g_attnh[(size_t)Bdim*Ldim*Ldim];
__device__ __align__(16) bf16  g_hh   [(size_t)Mrows*Edim];     // h*r bf16

// ---------------- helpers ----------------
__device__ __forceinline__ float sigmoidf_(float x){ return 1.f/(1.f+expf(-x)); }
__device__ __forceinline__ float siluf_(float x){ return x/(1.f+expf(-x)); }

__device__ __forceinline__ uint32_t smem_u32(const void* p){
    uint32_t a;
    asm("{ .reg .u64 t; cvta.to.shared.u64 t, %1; cvt.u32.u64 %0, t; }" : "=r"(a) : "l"(p));
    return a;
}
__device__ __forceinline__ void cp16(uint32_t dst, const void* src){
    asm volatile("cp.async.cg.shared.global [%0], [%1], 16;" :: "r"(dst), "l"(src));
}
#define CP_COMMIT() asm volatile("cp.async.commit_group;" ::: "memory")
#define CP_WAIT1()  asm volatile("cp.async.wait_group 1;" ::: "memory")

#define LDSM4(r0,r1,r2,r3,addr) \
    asm volatile("ldmatrix.sync.aligned.m8n8.x4.shared.b16 {%0,%1,%2,%3}, [%4];" \
                 : "=r"(r0),"=r"(r1),"=r"(r2),"=r"(r3) : "r"(addr))

__device__ __forceinline__ void mma_tf32(float* d, const uint32_t* a, const uint32_t* b){
    asm volatile(
        "mma.sync.aligned.m16n8k8.row.col.f32.tf32.tf32.f32 "
        "{%0,%1,%2,%3}, {%4,%5,%6,%7}, {%8,%9}, {%0,%1,%2,%3};\n"
        : "+f"(d[0]), "+f"(d[1]), "+f"(d[2]), "+f"(d[3])
        : "r"(a[0]), "r"(a[1]), "r"(a[2]), "r"(a[3]), "r"(b[0]), "r"(b[1]));
}
__device__ __forceinline__ void mma_bf16(float* d, const uint32_t* a, const uint32_t* b){
    asm volatile(
        "mma.sync.aligned.m16n8k16.row.col.f32.bf16.bf16.f32 "
        "{%0,%1,%2,%3}, {%4,%5,%6,%7}, {%8,%9}, {%0,%1,%2,%3};\n"
        : "+f"(d[0]), "+f"(d[1]), "+f"(d[2]), "+f"(d[3])
        : "r"(a[0]), "r"(a[1]), "r"(a[2]), "r"(a[3]), "r"(b[0]), "r"(b[1]));
}

__device__ __forceinline__ float blockReduceSum(float v) {
    __shared__ float sh[8];
    __shared__ float res;
    int lane = threadIdx.x & 31, wid = threadIdx.x >> 5;
    #pragma unroll
    for (int o = 16; o; o >>= 1) v += __shfl_xor_sync(0xffffffffu, v, o);
    if (lane == 0) sh[wid] = v;
    __syncthreads();
    if (wid == 0) {
        float t = (lane < 8) ? sh[lane] : 0.f;
        #pragma unroll
        for (int o = 4; o; o >>= 1) t += __shfl_xor_sync(0xffffffffu, t, o);
        if (lane == 0) res = t;
    }
    __syncthreads();
    return res;
}

// ---------------- elementwise kernels ----------------
__global__ void f2bf_kernel(const float* __restrict__ x, bf16* __restrict__ y)
{
    size_t i = ((size_t)blockIdx.x*blockDim.x + threadIdx.x)*4;
    float4 v = *(const float4*)(x + i);
    bf162 o0, o1;
    o0.x = __float2bfloat16(v.x); o0.y = __float2bfloat16(v.y);
    o1.x = __float2bfloat16(v.z); o1.y = __float2bfloat16(v.w);
    *(bf162*)(y + i)     = o0;
    *(bf162*)(y + i + 2) = o1;
}

// layernorm; writes fp32 and bf16 copies
__global__ void ln_kernel(const float* __restrict__ x, const float* __restrict__ w,
                          const float* __restrict__ bvec, float* __restrict__ y,
                          bf16* __restrict__ yh)
{
    const size_t row = blockIdx.x;
    float4 xv = ((const float4*)(x + row*Edim))[threadIdx.x];
    float mu = blockReduceSum(xv.x+xv.y+xv.z+xv.w) * (1.f/Edim);
    float dx = xv.x-mu, dy = xv.y-mu, dz = xv.z-mu, dw = xv.w-mu;
    float var = blockReduceSum(dx*dx+dy*dy+dz*dz+dw*dw) * (1.f/Edim);
    float rstd = rsqrtf(var + EPSV);
    float4 wv = ((const float4*)w)[threadIdx.x];
    float4 bv = ((const float4*)bvec)[threadIdx.x];
    float4 o;
    o.x = dx*rstd*wv.x + bv.x;
    o.y = dy*rstd*wv.y + bv.y;
    o.z = dz*rstd*wv.z + bv.z;
    o.w = dw*rstd*wv.w + bv.w;
    ((float4*)(y + row*Edim))[threadIdx.x] = o;
    bf162 h0, h1;
    h0.x = __float2bfloat16(o.x); h0.y = __float2bfloat16(o.y);
    h1.x = __float2bfloat16(o.z); h1.y = __float2bfloat16(o.w);
    *(bf162*)(yh + row*Edim + threadIdx.x*4)     = h0;
    *(bf162*)(yh + row*Edim + threadIdx.x*4 + 2) = h1;
}

// l2norm + affine, bf16 output
__global__ void l2norm_kernel(const float* __restrict__ in, int ldin,
                              bf16* __restrict__ out,
                              const float* __restrict__ gamma, const float* __restrict__ beta)
{
    const size_t row = blockIdx.x;
    const int z = threadIdx.x;
    float x = in[row*(size_t)ldin + z];
    float ss = blockReduceSum(x*x);
    float d = fmaxf(sqrtf(ss), EPSV);
    out[row*Zdim + z] = __float2bfloat16((x/d) * (gamma[z] + 1.f) + beta[z]);
}

// vt[b][e][c] = v[(c*B+b)*E + e]   (bf16)
__global__ void transpose_v(const bf16* __restrict__ v, bf16* __restrict__ vt)
{
    __shared__ bf16 t[32][33];
    const int b  = blockIdx.z;
    const int c0 = blockIdx.x*32, e0 = blockIdx.y*32;
    const int x = threadIdx.x, y = threadIdx.y;
    #pragma unroll
    for (int i = 0; i < 32; i += 8)
        t[y+i][x] = v[(size_t)(c0+y+i)*Bdim*Edim + (size_t)b*Edim + e0 + x];
    __syncthreads();
    #pragma unroll
    for (int i = 0; i < 32; i += 8)
        vt[((size_t)b*Edim + e0+y+i)*Ldim + c0 + x] = t[x][y+i];
}

enum { EPI_RAW=1, EPI_SILU=2, EPI_OUT=3, EPI_SCORE=4, EPI_AV=5, EPI_QR=6, EPI_SIG=7 };

// =====================================================================
// tf32 HMMA GEMM (NT) — u projection only (sigmoid epilogue)
// =====================================================================
#define BM 128
#define BN 128
#define BK 32
#define NSTAGE 3
#define PAD 36
#define TBYTES (128*PAD*4)
#define BUFBYTES (2*TBYTES)
#define SMEM_BYTES (NSTAGE*BUFBYTES) // 110592

__global__ void __launch_bounds__(256, 2)
tc_gemm_u(const float* __restrict__ A, size_t sAm,
          const float* __restrict__ Bp, size_t sB,
          const float* __restrict__ bias,
          float* __restrict__ Y, size_t sYm, int Kdim)
{
    extern __shared__ __align__(16) float smem[];
    const uint32_t smem_b = smem_u32(smem);
    const int tid  = threadIdx.x;
    const int warp = tid >> 5, lane = tid & 31;
    const int g = lane >> 2, tg = lane & 3;
    const int wm = warp >> 1, wn = warp & 1;
    const int row0 = blockIdx.y * BM;
    const int col0 = blockIdx.x * BN;

    float acc[2][8][4];
    #pragma unroll
    for (int i=0;i<2;i++)
        #pragma unroll
        for (int j=0;j<8;j++)
            #pragma unroll
            for (int t=0;t<4;t++) acc[i][j][t]=0.f;

    const int lm8 = lane & 7, lq = lane >> 3;
    uint32_t a_addr[2], b_addr[4];
    #pragma unroll
    for (int i = 0; i < 2; i++)
        a_addr[i] = smem_b + (uint32_t)((wm*32 + i*16 + (lq&1)*8 + lm8)*PAD + (lq>>1)*4)*4;
    #pragma unroll
    for (int jj = 0; jj < 4; jj++)
        b_addr[jj] = smem_b + TBYTES + (uint32_t)((wn*64 + jj*16 + (lq>>1)*8 + lm8)*PAD + (lq&1)*4)*4;

    const int lr  = tid >> 3;
    const int lc4 = (tid & 7) << 2;
    const float* Ag = A  + (size_t)row0*sAm;
    const float* Bg = Bp + (size_t)col0*sB;

    auto load_tile = [&](int kt, int s){
        const uint32_t ab = smem_b + s*BUFBYTES;
        const uint32_t bb = ab + TBYTES;
        const float* Agk = Ag + (size_t)kt*BK;
        const float* Bgk = Bg + (size_t)kt*BK;
        #pragma unroll
        for (int i = 0; i < 4; i++) {
            int r = lr + i*32;
            cp16(ab + (uint32_t)(r*PAD + lc4)*4, Agk + (size_t)r*sAm + lc4);
            cp16(bb + (uint32_t)(r*PAD + lc4)*4, Bgk + (size_t)r*sB  + lc4);
        }
    };

    const int KT = Kdim / BK;
    load_tile(0, 0); CP_COMMIT();
    if (KT > 1) { load_tile(1, 1); } CP_COMMIT();

    for (int kt = 0; kt < KT; kt++) {
        CP_WAIT1();
        __syncthreads();
        const uint32_t soff = (uint32_t)((kt % NSTAGE)*BUFBYTES);
        #pragma unroll
        for (int ks = 0; ks < 4; ks++) {
            const uint32_t koff = soff + ks*32;
            uint32_t a[2][4], b[8][2];
            LDSM4(a[0][0], a[0][1], a[0][2], a[0][3], a_addr[0] + koff);
            LDSM4(a[1][0], a[1][1], a[1][2], a[1][3], a_addr[1] + koff);
            #pragma unroll
            for (int jj = 0; jj < 4; jj++)
                LDSM4(b[2*jj][0], b[2*jj][1], b[2*jj+1][0], b[2*jj+1][1], b_addr[jj] + koff);
            #pragma unroll
            for (int i = 0; i < 2; i++)
                #pragma unroll
                for (int j = 0; j < 8; j++)
                    mma_tf32(acc[i][j], a[i], b[j]);
        }
        if (kt + 2 < KT) load_tile(kt+2, (kt+2) % NSTAGE);
        CP_COMMIT();
    }

    #pragma unroll
    for (int i = 0; i < 2; i++) {
        #pragma unroll
        for (int j = 0; j < 8; j++) {
            const int rr = row0 + wm*32 + i*16 + g;
            const int cc = col0 + wn*64 + j*8 + tg*2;
            #pragma unroll
            for (int h = 0; h < 2; h++) {
                const int r = rr + h*8;
                float v0 = sigmoidf_(acc[i][j][h*2+0] + bias[cc]);
                float v1 = sigmoidf_(acc[i][j][h*2+1] + bias[cc+1]);
                *(float2*)(Y + (size_t)r*sYm + cc) = make_float2(v0, v1);
            }
        }
    }
}

// =====================================================================
// bf16 HMMA GEMM (NT): m16n8k16, BK=64 bf16, 3-stage cp.async, ldmatrix.
// =====================================================================
#define HBK 64
#define HTB (128*144)                 // 18432 B (144 B/row)
#define HBUF (2*HTB)
#define HSMEM (NSTAGE*HBUF)           // 110592 B

template<int EPI, bool OUT_BF16>
__global__ void __launch_bounds__(256, 2)
hgemm(const bf16* __restrict__ A, size_t sAm, size_t batchA,
      const bf16* __restrict__ Bp, size_t sB, size_t batchB,
      const float* __restrict__ bias,
      void* __restrict__ Yv, size_t sYm, size_t batchY,
      int Kdim,
      const float* __restrict__ e0, size_t e0s, size_t batchE0,
      const float* __restrict__ e1,
      const float* __restrict__ relpos)
{
    extern __shared__ __align__(16) char hsm[];
    const uint32_t smem_b = smem_u32(hsm);
    const int tid  = threadIdx.x;
    const int warp = tid >> 5, lane = tid & 31;
    const int g = lane >> 2, tg = lane & 3;
    const int wm = warp >> 1, wn = warp & 1;
    const int row0 = blockIdx.y * BM;
    const int col0 = blockIdx.x * BN;
    const int bz   = blockIdx.z;

    A  += (size_t)bz * batchA;
    Bp += (size_t)bz * batchB;
    const float* e0b = e0 ? e0 + (size_t)bz * batchE0 : e0;

    float acc[2][8][4];
    #pragma unroll
    for (int i=0;i<2;i++)
        #pragma unroll
        for (int j=0;j<8;j++)
            #pragma unroll
            for (int t=0;t<4;t++) acc[i][j][t]=0.f;

    const int lm8 = lane & 7, lq = lane >> 3;
    uint32_t a_addr[2], b_addr[4];
    #pragma unroll
    for (int i = 0; i < 2; i++)
        a_addr[i] = smem_b + (uint32_t)((wm*32 + i*16 + (lq&1)*8 + lm8)*144 + (lq>>1)*16);
    #pragma unroll
    for (int jj = 0; jj < 4; jj++)
        b_addr[jj] = smem_b + HTB + (uint32_t)((wn*64 + jj*16 + (lq>>1)*8 + lm8)*144 + (lq&1)*16);

    const int lr  = tid >> 3;
    const int lc8 = (tid & 7) << 3;
    const bf16* Ag = A  + (size_t)row0*sAm;
    const bf16* Bg = Bp + (size_t)col0*sB;

    auto load_tile = [&](int kt, int s){
        const uint32_t ab = smem_b + s*HBUF;
        const uint32_t bb = ab + HTB;
        const bf16* Agk = Ag + (size_t)kt*HBK;
        const bf16* Bgk = Bg + (size_t)kt*HBK;
        #pragma unroll
        for (int i = 0; i < 4; i++) {
            int r = lr + i*32;
            cp16(ab + (uint32_t)(r*144 + lc8*2), Agk + (size_t)r*sAm + lc8);
            cp16(bb + (uint32_t)(r*144 + lc8*2), Bgk + (size_t)r*sB  + lc8);
        }
    };

    const int KT = Kdim / HBK;
    load_tile(0, 0); CP_COMMIT();
    if (KT > 1) { load_tile(1, 1); } CP_COMMIT();

    for (int kt = 0; kt < KT; kt++) {
        CP_WAIT1();
        __syncthreads();
        const uint32_t soff = (uint32_t)((kt % NSTAGE)*HBUF);
        #pragma unroll
        for (int ks = 0; ks < 4; ks++) {
            const uint32_t koff = soff + ks*32;
            uint32_t a[2][4], b[8][2];
            LDSM4(a[0][0], a[0][1], a[0][2], a[0][3], a_addr[0] + koff);
            LDSM4(a[1][0], a[1][1], a[1][2], a[1][3], a_addr[1] + koff);
            #pragma unroll
            for (int jj = 0; jj < 4; jj++)
                LDSM4(b[2*jj][0], b[2*jj][1], b[2*jj+1][0], b[2*jj+1][1], b_addr[jj] + koff);
            #pragma unroll
            for (int i = 0; i < 2; i++)
                #pragma unroll
                for (int j = 0; j < 8; j++)
                    mma_bf16(acc[i][j], a[i], b[j]);
        }
        if (kt + 2 < KT) load_tile(kt+2, (kt+2) % NSTAGE);
        CP_COMMIT();
    }

    // ---- epilogue ----
    #pragma unroll
    for (int i = 0; i < 2; i++) {
        #pragma unroll
        for (int j = 0; j < 8; j++) {
            const int rr = row0 + wm*32 + i*16 + g;
            const int cc = col0 + wn*64 + j*8 + tg*2;
            #pragma unroll
            for (int h = 0; h < 2; h++) {
                const int r = rr + h*8;
                float v0 = acc[i][j][h*2+0];
                float v1 = acc[i][j][h*2+1];
                int cg = cc;     // output column (possibly remapped)
                if (EPI == EPI_RAW) {
                    v0 += bias[cc];   v1 += bias[cc+1];
                } else if (EPI == EPI_SILU) {
                    v0 = siluf_(v0 + bias[cc]); v1 = siluf_(v1 + bias[cc+1]);
                } else if (EPI == EPI_QR) {
                    cg = (cc < Zdim) ? cc : cc + Edim;   // pack col -> base col
                    v0 += bias[cg];   v1 += bias[cg+1];
                    if (cc >= Zdim) { v0 = siluf_(v0); v1 = siluf_(v1); }
                } else if (EPI == EPI_OUT) {
                    v0 += bias[cc];   v1 += bias[cc+1];
                    float u0 = e0b[(size_t)r*NBASE + Zdim + cc];
                    float u1 = e0b[(size_t)r*NBASE + Zdim + cc+1];
                    float q0 = e1[(size_t)r*Edim + cc];
                    float q1 = e1[(size_t)r*Edim + cc+1];
                    v0 = q0 + u0*(v0 - q0);
                    v1 = q1 + u1*(v1 - q1);
                } else if (EPI == EPI_SCORE) {
                    v0 = fmaxf(v0*SCALEV + relpos[2047 + cc   - r], 0.f); v0 *= v0;
                    v1 = fmaxf(v1*SCALEV + relpos[2047 + cc+1 - r], 0.f); v1 *= v1;
                } else if (EPI == EPI_AV) {
                    v0 *= e0b[(size_t)r*e0s + cc];
                    v1 *= e0b[(size_t)r*e0s + cc+1];
                }
                if (OUT_BF16) {
                    bf16* Y = (bf16*)Yv + (size_t)bz*batchY;
                    bf162 o; o.x = __float2bfloat16(v0); o.y = __float2bfloat16(v1);
                    *(bf162*)(Y + (size_t)r*sYm + cg) = o;
                } else {
                    float* Y = (float*)Yv + (size_t)bz*batchY;
                    *(float2*)(Y + (size_t)r*sYm + cg) = make_float2(v0, v1);
                }
            }
        }
    }
}

// ---------------- launch ----------------
extern "C" void kernel_launch(void* const* d_in, const int* /*in_sizes*/, int /*n_in*/,
                              void* d_out, int /*out_size*/)
{
    const float* query  = (const float*)d_in[0];
    const float* key_in = (const float*)d_in[1];
    const float* value  = (const float*)d_in[2];
    const float* ln_w   = (const float*)d_in[3];
    const float* ln_b   = (const float*)d_in[4];
    const float* Wv     = (const float*)d_in[5];
    const float* bv     = (const float*)d_in[6];
    const float* Wk     = (const float*)d_in[7];
    const float* bk     = (const float*)d_in[8];
    const float* Wqru   = (const float*)d_in[9];
    const float* bqru   = (const float*)d_in[10];
    const float* Wh     = (const float*)d_in[11];
    const float* bh     = (const float*)d_in[12];
    const float* gamma  = (const float*)d_in[13];
    const float* beta   = (const float*)d_in[14];
    const float* relpos = (const float*)d_in[15];
    float* out = (float*)d_out;

    float *nq, *base, *kf;
    bf16 *nqh, *khin, *vhin, *wkh, *wvh, *whh, *wqrh, *qh, *kh, *vh, *vth, *attnh, *hh;
    cudaGetSymbolAddress((void**)&nq,    g_nq);
    cudaGetSymbolAddress((void**)&nqh,   g_nqh);
    cudaGetSymbolAddress((void**)&base,  g_base);
    cudaGetSymbolAddress((void**)&kf,    g_kf);
    cudaGetSymbolAddress((void**)&khin,  g_khin);
    cudaGetSymbolAddress((void**)&vhin,  g_vhin);
    cudaGetSymbolAddress((void**)&wkh,   g_wkh);
    cudaGetSymbolAddress((void**)&wvh,   g_wvh);
    cudaGetSymbolAddress((void**)&whh,   g_whh);
    cudaGetSymbolAddress((void**)&wqrh,  g_wqrh);
    cudaGetSymbolAddress((void**)&qh,    g_qh);
    cudaGetSymbolAddress((void**)&kh,    g_kh);
    cudaGetSymbolAddress((void**)&vh,    g_vh);
    cudaGetSymbolAddress((void**)&vth,   g_vth);
    cudaGetSymbolAddress((void**)&attnh, g_attnh);
    cudaGetSymbolAddress((void**)&hh,    g_hh);

    cudaFuncSetAttribute(tc_gemm_u,              cudaFuncAttributeMaxDynamicSharedMemorySize, SMEM_BYTES);
    cudaFuncSetAttribute(hgemm<EPI_RAW,  false>, cudaFuncAttributeMaxDynamicSharedMemorySize, HSMEM);
    cudaFuncSetAttribute(hgemm<EPI_SILU, true>,  cudaFuncAttributeMaxDynamicSharedMemorySize, HSMEM);
    cudaFuncSetAttribute(hgemm<EPI_QR,   false>, cudaFuncAttributeMaxDynamicSharedMemorySize, HSMEM);
    cudaFuncSetAttribute(hgemm<EPI_SCORE,true>,  cudaFuncAttributeMaxDynamicSharedMemorySize, HSMEM);
    cudaFuncSetAttribute(hgemm<EPI_AV,   true>,  cudaFuncAttributeMaxDynamicSharedMemorySize, HSMEM);
    cudaFuncSetAttribute(hgemm<EPI_OUT,  false>, cudaFuncAttributeMaxDynamicSharedMemorySize, HSMEM);

    // conversions to bf16
    f2bf_kernel<<<(size_t)Mrows*Edim/1024, 256>>>(key_in, khin);
    f2bf_kernel<<<(size_t)Mrows*Edim/1024, 256>>>(value,  vhin);
    f2bf_kernel<<<(size_t)Zdim*Edim/1024,  256>>>(Wk, wkh);
    f2bf_kernel<<<(size_t)Edim*Edim/1024,  256>>>(Wv, wvh);
    f2bf_kernel<<<(size_t)Edim*Edim/1024,  256>>>(Wh, whh);
    // packed q|r weights: rows [0,256) = Wqru q rows; rows [256,1280) = Wqru r rows
    f2bf_kernel<<<(size_t)Zdim*Edim/1024,  256>>>(Wqru, wqrh);
    f2bf_kernel<<<(size_t)Edim*Edim/1024,  256>>>(Wqru + (size_t)(Zdim+Edim)*Edim, wqrh + (size_t)Zdim*Edim);

    // 1. nq = layernorm(query)  (fp32 + bf16)
    ln_kernel<<<Mrows, 256>>>(query, ln_w, ln_b, nq, nqh);

    // 2a. u = sigmoid(nq @ Wu^T + bu)  (tf32, N=1024) -> base cols [Z, Z+E)
    tc_gemm_u<<<dim3(Edim/BN, Mrows/BM), 256, SMEM_BYTES>>>(
        nq, Edim, Wqru + (size_t)Zdim*Edim, Edim, bqru + Zdim, base + Zdim, NBASE, Edim);

    // 2b. q|r = nq @ Wqr^T + b  (bf16, N=1280 packed) -> base cols [0,Z) and [Z+E, NBASE)
    hgemm<EPI_QR,false><<<dim3(NQR/BN, Mrows/BM, 1), 256, HSMEM>>>(
        nqh, Edim, 0, wqrh, Edim, 0, bqru, base, NBASE, 0, Edim,
        nullptr, 0, 0, nullptr, nullptr);

    // 3. kf = key_in @ Wk^T + bk
    hgemm<EPI_RAW,false><<<dim3(Zdim/BN, Mrows/BM, 1), 256, HSMEM>>>(
        khin, Edim, 0, wkh, Edim, 0, bk, kf, Zdim, 0, Edim,
        nullptr, 0, 0, nullptr, nullptr);

    // 4. vh = silu(value @ Wv^T + bv)
    hgemm<EPI_SILU,true><<<dim3(Edim/BN, Mrows/BM, 1), 256, HSMEM>>>(
        vhin, Edim, 0, wvh, Edim, 0, bv, vh, Edim, 0, Edim,
        nullptr, 0, 0, nullptr, nullptr);

    // 5/6. l2norms -> bf16 q,k
    l2norm_kernel<<<Mrows, 256>>>(base, NBASE, qh, gamma, beta);
    l2norm_kernel<<<Mrows, 256>>>(kf, Zdim, kh, gamma + Zdim, beta + Zdim);

    // 6b. vth[b][e][c]
    transpose_v<<<dim3(Ldim/32, Edim/32, Bdim), dim3(32,8)>>>(vh, vth);

    // 7. attn = relu(q.k*scale + relbias)^2
    hgemm<EPI_SCORE,true><<<dim3(Ldim/BN, Ldim/BM, Bdim), 256, HSMEM>>>(
        qh, (size_t)Bdim*Zdim, Zdim,
        kh, (size_t)Bdim*Zdim, Zdim,
        nullptr, attnh, Ldim, (size_t)Ldim*Ldim, Zdim,
        nullptr, 0, 0, nullptr, relpos);

    // 8. hh = (attn @ vth^T) * r
    hgemm<EPI_AV,true><<<dim3(Edim/BN, Ldim/BM, Bdim), 256, HSMEM>>>(
        attnh, Ldim, (size_t)Ldim*Ldim,
        vth, Ldim, (size_t)Edim*Ldim,
        nullptr, hh, (size_t)Bdim*Edim, Edim, Ldim,
        base + Zdim + Edim, (size_t)Bdim*NBASE, NBASE, nullptr, nullptr);

    // 9. out = query + u * ((hh @ Wh^T + bh) - query)
    hgemm<EPI_OUT,false><<<dim3(Edim/BN, Mrows/BM, 1), 256, HSMEM>>>(
        hh, Edim, 0, whh, Edim, 0, bh, out, Edim, 0, Edim,
        base, 0, 0, query, nullptr);
}